// round 1
// baseline (speedup 1.0000x reference)
#include <cuda_runtime.h>
#include <cuda_bf16.h>
#include <math.h>

#define BSZ  2
#define SEQL 2048
#define DIMM 4096
#define NH   32
#define NKV  8
#define HD   128

// Scratch (allocation-free rule: __device__ globals)
__device__ float g_q[BSZ * SEQL * NH * HD];      // 64 MB
__device__ float g_k[BSZ * SEQL * NKV * HD];     // 16 MB
__device__ float g_v[BSZ * SEQL * NKV * HD];     // 16 MB
__device__ float g_attn[BSZ * SEQL * NH * HD];   // 64 MB

// ---------------------------------------------------------------------------
// Tiled fp32 SGEMM: C[M,N] = A[M,K] @ B[K,N], all row-major.
// BM=BN=128, BK=8, 256 threads, 8x8 per thread (rows trow*8.., cols split
// {tcol*4, 64+tcol*4} to keep smem conflicts at 2-way).
// ---------------------------------------------------------------------------
__global__ __launch_bounds__(256) void sgemm128(
    const float* __restrict__ A, const float* __restrict__ B,
    float* __restrict__ C, int M, int N, int K)
{
    __shared__ float As[8][132];   // padded: conflict-free row reads
    __shared__ float Bs[8][128];

    const int bx = blockIdx.x;     // N tile
    const int by = blockIdx.y;     // M tile
    const int tid  = threadIdx.x;
    const int tcol = tid & 15;
    const int trow = tid >> 4;

    A += (size_t)by * 128 * K;
    B += (size_t)bx * 128;
    C += (size_t)by * 128 * N + (size_t)bx * 128;

    const int aRow = tid >> 1;          // 0..127
    const int aCol = (tid & 1) * 4;     // 0 or 4
    const int bRow = tid >> 5;          // 0..7
    const int bCol = (tid & 31) * 4;    // 0..124

    float acc[8][8];
#pragma unroll
    for (int i = 0; i < 8; i++)
#pragma unroll
        for (int j = 0; j < 8; j++) acc[i][j] = 0.f;

    for (int k0 = 0; k0 < K; k0 += 8) {
        float4 av = *(const float4*)(A + (size_t)aRow * K + k0 + aCol);
        As[aCol + 0][aRow] = av.x;
        As[aCol + 1][aRow] = av.y;
        As[aCol + 2][aRow] = av.z;
        As[aCol + 3][aRow] = av.w;
        *(float4*)(&Bs[bRow][bCol]) =
            *(const float4*)(B + (size_t)(k0 + bRow) * N + bCol);
        __syncthreads();

#pragma unroll
        for (int k = 0; k < 8; k++) {
            float4 a0 = *(const float4*)(&As[k][trow * 8]);
            float4 a1 = *(const float4*)(&As[k][trow * 8 + 4]);
            float4 b0 = *(const float4*)(&Bs[k][tcol * 4]);
            float4 b1 = *(const float4*)(&Bs[k][64 + tcol * 4]);
            float rm[8] = {a0.x, a0.y, a0.z, a0.w, a1.x, a1.y, a1.z, a1.w};
            float rn[8] = {b0.x, b0.y, b0.z, b0.w, b1.x, b1.y, b1.z, b1.w};
#pragma unroll
            for (int i = 0; i < 8; i++)
#pragma unroll
                for (int j = 0; j < 8; j++) acc[i][j] += rm[i] * rn[j];
        }
        __syncthreads();
    }

#pragma unroll
    for (int i = 0; i < 8; i++) {
        float* cp = C + (size_t)(trow * 8 + i) * N;
        *(float4*)(cp + tcol * 4) =
            make_float4(acc[i][0], acc[i][1], acc[i][2], acc[i][3]);
        *(float4*)(cp + 64 + tcol * 4) =
            make_float4(acc[i][4], acc[i][5], acc[i][6], acc[i][7]);
    }
}

// ---------------------------------------------------------------------------
// RoPE (interleaved pairs), in place. Layout (b,s,h,d) contiguous;
// float2 index == ((b*seq+s)*nheads + h)*64 + i.
// ---------------------------------------------------------------------------
__global__ void rope_kernel(float* __restrict__ t,
                            const float* __restrict__ cosb,
                            const float* __restrict__ sinb,
                            int nheads, int seq, int total)
{
    int idx = blockIdx.x * blockDim.x + threadIdx.x;
    if (idx >= total) return;
    int i = idx & 63;
    int s = ((idx >> 6) / nheads) % seq;
    float2* p = (float2*)t + idx;
    float2 v = *p;
    float c  = cosb[s * 64 + i];
    float sn = sinb[s * 64 + i];
    *p = make_float2(v.x * c - v.y * sn, v.x * sn + v.y * c);
}

// ---------------------------------------------------------------------------
// Causal flash attention, fp32, BQ=BK=64, HD=128, online softmax.
// grid (seq/64, NH, BSZ), 256 threads.
// smem: Qs[64][132] | Ks (XOR-swizzled f4 [64][32]) | Vs[64][128] |
//       S[64][68] | m/l/corr[64]
// ---------------------------------------------------------------------------
#define QS_STRIDE 132
#define S_STRIDE  68

__global__ __launch_bounds__(256, 1) void flash_attn(
    const float* __restrict__ Qg, const float* __restrict__ Kg,
    const float* __restrict__ Vg, float* __restrict__ Og, int seq)
{
    extern __shared__ float sm[];
    float* Qs   = sm;                       // 64*132 = 8448
    float* Ks4  = Qs  + 64 * QS_STRIDE;     // 64*128 = 8192 (swizzled float4)
    float* Vs   = Ks4 + 64 * 128;           // 8192
    float* S    = Vs  + 64 * 128;           // 64*68 = 4352
    float* mrow = S   + 64 * S_STRIDE;      // 64
    float* lrow = mrow + 64;
    float* crow = lrow + 64;

    const int qt  = blockIdx.x;
    const int h   = blockIdx.y;
    const int b   = blockIdx.z;
    const int kvh = h >> 2;                 // N_REP = 4
    const int tid = threadIdx.x;
    const int tx  = tid & 15;
    const int ty  = tid >> 4;

    const float scale = 0.08838834764831845f;  // 1/sqrt(128)

    const float* Qbase = Qg + ((size_t)b * seq) * (NH  * HD) + h   * HD;
    const float* Kbase = Kg + ((size_t)b * seq) * (NKV * HD) + kvh * HD;
    const float* Vbase = Vg + ((size_t)b * seq) * (NKV * HD) + kvh * HD;

    // Load Q tile (64 rows x 128)
#pragma unroll
    for (int i = 0; i < 8; i++) {
        int id = tid + i * 256;
        int r = id >> 5, f = id & 31;
        float4 v = *(const float4*)(Qbase + (size_t)(qt * 64 + r) * (NH * HD) + f * 4);
        *(float4*)(Qs + r * QS_STRIDE + f * 4) = v;
    }
    if (tid < 64) { mrow[tid] = -INFINITY; lrow[tid] = 0.f; }

    float o[4][8];
#pragma unroll
    for (int i = 0; i < 4; i++)
#pragma unroll
        for (int j = 0; j < 8; j++) o[i][j] = 0.f;

    __syncthreads();

    for (int kt = 0; kt <= qt; kt++) {
        // Load K (swizzled) and V tiles
#pragma unroll
        for (int i = 0; i < 8; i++) {
            int id = tid + i * 256;
            int r = id >> 5, f = id & 31;
            size_t grow = (size_t)(kt * 64 + r) * (NKV * HD);
            float4 kv = *(const float4*)(Kbase + grow + f * 4);
            *(float4*)(Ks4 + r * 128 + ((f ^ (r & 31)) << 2)) = kv;
            float4 vv = *(const float4*)(Vbase + grow + f * 4);
            *(float4*)(Vs + r * 128 + f * 4) = vv;
        }
        __syncthreads();

        // Scores: 4x4 per thread, rows ty*4.., cols tx*4..
        float acc[4][4];
#pragma unroll
        for (int i = 0; i < 4; i++)
#pragma unroll
            for (int j = 0; j < 4; j++) acc[i][j] = 0.f;

#pragma unroll 4
        for (int f = 0; f < 32; f++) {
            float4 qv[4], kv[4];
#pragma unroll
            for (int i = 0; i < 4; i++)
                qv[i] = *(const float4*)(Qs + (ty * 4 + i) * QS_STRIDE + f * 4);
#pragma unroll
            for (int j = 0; j < 4; j++) {
                int c = tx * 4 + j;
                kv[j] = *(const float4*)(Ks4 + c * 128 + ((f ^ (c & 31)) << 2));
            }
#pragma unroll
            for (int i = 0; i < 4; i++)
#pragma unroll
                for (int j = 0; j < 4; j++)
                    acc[i][j] += qv[i].x * kv[j].x + qv[i].y * kv[j].y +
                                 qv[i].z * kv[j].z + qv[i].w * kv[j].w;
        }

        // Store scores with scale + causal mask
        const int q0 = qt * 64, k0 = kt * 64;
#pragma unroll
        for (int i = 0; i < 4; i++) {
            int qg = q0 + ty * 4 + i;
            int kc = k0 + tx * 4;
            float4 sv;
            sv.x = (kc + 0 > qg) ? -1e9f : acc[i][0] * scale;
            sv.y = (kc + 1 > qg) ? -1e9f : acc[i][1] * scale;
            sv.z = (kc + 2 > qg) ? -1e9f : acc[i][2] * scale;
            sv.w = (kc + 3 > qg) ? -1e9f : acc[i][3] * scale;
            *(float4*)(S + (ty * 4 + i) * S_STRIDE + tx * 4) = sv;
        }
        __syncthreads();

        // Online softmax, one thread per row
        if (tid < 64) {
            float* srow = S + tid * S_STRIDE;
            float mold = mrow[tid];
            float mx = mold;
#pragma unroll 8
            for (int c = 0; c < 64; c++) mx = fmaxf(mx, srow[c]);
            float corr = __expf(mold - mx);
            float lsum = 0.f;
#pragma unroll 8
            for (int c = 0; c < 64; c++) {
                float p = __expf(srow[c] - mx);
                srow[c] = p;
                lsum += p;
            }
            mrow[tid] = mx;
            lrow[tid] = lrow[tid] * corr + lsum;
            crow[tid] = corr;
        }
        __syncthreads();

        // O = O*corr + P @ V  (rows ty*4.., cols {tx*4, 64+tx*4})
        float cr[4];
#pragma unroll
        for (int i = 0; i < 4; i++) cr[i] = crow[ty * 4 + i];
#pragma unroll
        for (int i = 0; i < 4; i++)
#pragma unroll
            for (int j = 0; j < 8; j++) o[i][j] *= cr[i];

#pragma unroll 2
        for (int k = 0; k < 64; k++) {
            float pv[4];
#pragma unroll
            for (int i = 0; i < 4; i++) pv[i] = S[(ty * 4 + i) * S_STRIDE + k];
            float4 va = *(const float4*)(Vs + k * 128 + tx * 4);
            float4 vb = *(const float4*)(Vs + k * 128 + 64 + tx * 4);
#pragma unroll
            for (int i = 0; i < 4; i++) {
                o[i][0] += pv[i] * va.x;  o[i][1] += pv[i] * va.y;
                o[i][2] += pv[i] * va.z;  o[i][3] += pv[i] * va.w;
                o[i][4] += pv[i] * vb.x;  o[i][5] += pv[i] * vb.y;
                o[i][6] += pv[i] * vb.z;  o[i][7] += pv[i] * vb.w;
            }
        }
        __syncthreads();
    }

    // Epilogue: divide by l, write (b, s, h, d)
#pragma unroll
    for (int i = 0; i < 4; i++) {
        float linv = 1.0f / lrow[ty * 4 + i];
        size_t orow = ((size_t)b * seq + qt * 64 + ty * 4 + i) * (NH * HD) + h * HD;
        *(float4*)(Og + orow + tx * 4) =
            make_float4(o[i][0] * linv, o[i][1] * linv, o[i][2] * linv, o[i][3] * linv);
        *(float4*)(Og + orow + 64 + tx * 4) =
            make_float4(o[i][4] * linv, o[i][5] * linv, o[i][6] * linv, o[i][7] * linv);
    }
}

// ---------------------------------------------------------------------------
extern "C" void kernel_launch(void* const* d_in, const int* in_sizes, int n_in,
                              void* d_out, int out_size)
{
    const float* x  = (const float*)d_in[0];
    const float* wq = (const float*)d_in[1];
    const float* wk = (const float*)d_in[2];
    const float* wv = (const float*)d_in[3];
    const float* wo = (const float*)d_in[4];
    const float* fc = (const float*)d_in[7];
    const float* fs = (const float*)d_in[8];
    float* out = (float*)d_out;

    float *q, *k, *v, *attn;
    cudaGetSymbolAddress((void**)&q,    g_q);
    cudaGetSymbolAddress((void**)&k,    g_k);
    cudaGetSymbolAddress((void**)&v,    g_v);
    cudaGetSymbolAddress((void**)&attn, g_attn);

    const int M = BSZ * SEQL;  // 4096

    // QKV projections
    sgemm128<<<dim3(NH * HD / 128,  M / 128), 256>>>(x, wq, q, M, NH * HD,  DIMM);
    sgemm128<<<dim3(NKV * HD / 128, M / 128), 256>>>(x, wk, k, M, NKV * HD, DIMM);
    sgemm128<<<dim3(NKV * HD / 128, M / 128), 256>>>(x, wv, v, M, NKV * HD, DIMM);

    // RoPE (start_pos = 0)
    int qpairs = BSZ * SEQL * NH  * 64;
    int kpairs = BSZ * SEQL * NKV * 64;
    rope_kernel<<<(qpairs + 255) / 256, 256>>>(q, fc, fs, NH,  SEQL, qpairs);
    rope_kernel<<<(kpairs + 255) / 256, 256>>>(k, fc, fs, NKV, SEQL, kpairs);

    // Flash attention
    const int smem_bytes = (64 * QS_STRIDE + 64 * 128 + 64 * 128 +
                            64 * S_STRIDE + 192) * sizeof(float);
    cudaFuncSetAttribute(flash_attn, cudaFuncAttributeMaxDynamicSharedMemorySize,
                         smem_bytes);
    flash_attn<<<dim3(SEQL / 64, NH, BSZ), 256, smem_bytes>>>(q, k, v, attn, SEQL);

    // Output projection
    sgemm128<<<dim3(DIMM / 128, M / 128), 256>>>(attn, wo, out, M, DIMM, DIMM);
}

// round 3
// speedup vs baseline: 2.4110x; 2.4110x over previous
#include <cuda_runtime.h>
#include <cuda_fp16.h>
#include <math.h>
#include <stdint.h>

#define BSZ  2
#define SEQL 2048
#define DIMM 4096
#define NH   32
#define NKV  8
#define HD   128
#define MTOT (BSZ * SEQL)          // 4096

// ---------------- scratch (__device__ globals) ----------------------------
__device__ float  g_q[MTOT * NH * HD];
__device__ float  g_k[MTOT * NKV * HD];
__device__ float  g_v[MTOT * NKV * HD];
__device__ __half g_xh[MTOT * DIMM];
__device__ __half g_wqh[DIMM * NH * HD];
__device__ __half g_wkh[DIMM * NKV * HD];
__device__ __half g_wvh[DIMM * NKV * HD];
__device__ __half g_woh[DIMM * DIMM];
__device__ __half g_attnh[MTOT * NH * HD];

// ---------------- PTX helpers ---------------------------------------------
__device__ __forceinline__ uint32_t smem_u32(const void* p) {
    uint32_t a;
    asm("{ .reg .u64 t; cvta.to.shared.u64 t, %1; cvt.u32.u64 %0, t; }"
        : "=r"(a) : "l"(p));
    return a;
}
__device__ __forceinline__ void cp_async16(uint32_t dst, const void* src) {
    asm volatile("cp.async.cg.shared.global [%0], [%1], 16;" :: "r"(dst), "l"(src));
}
#define CP_COMMIT() asm volatile("cp.async.commit_group;" ::: "memory")
#define CP_WAIT(n)  asm volatile("cp.async.wait_group %0;" :: "n"(n) : "memory")

#define LDSM_X4(R, addr) \
    asm volatile("ldmatrix.sync.aligned.m8n8.x4.shared.b16 {%0,%1,%2,%3}, [%4];" \
        : "=r"((R)[0]), "=r"((R)[1]), "=r"((R)[2]), "=r"((R)[3]) : "r"(addr))
#define LDSM_X4_T(R, addr) \
    asm volatile("ldmatrix.sync.aligned.m8n8.x4.trans.shared.b16 {%0,%1,%2,%3}, [%4];" \
        : "=r"((R)[0]), "=r"((R)[1]), "=r"((R)[2]), "=r"((R)[3]) : "r"(addr))

#define MMA16816(D, A, B0, B1) \
    asm volatile("mma.sync.aligned.m16n8k16.row.col.f32.f16.f16.f32 " \
        "{%0,%1,%2,%3}, {%4,%5,%6,%7}, {%8,%9}, {%0,%1,%2,%3};" \
        : "+f"((D)[0]), "+f"((D)[1]), "+f"((D)[2]), "+f"((D)[3]) \
        : "r"((A)[0]), "r"((A)[1]), "r"((A)[2]), "r"((A)[3]), "r"(B0), "r"(B1))

// ---------------- fp16 mma.sync GEMM: C[M,N] = A[M,K] @ B[K,N] -------------
// A row-major fp16, B row-major fp16, C fp32. BM=BN=128, BK=64, 4 stages.
#define GBM 128
#define GBN 128
#define GBK 64
#define GST 4
#define A_STAGE 16384                 // 128 rows * 128 B
#define B_STAGE 16384                 // 64 rows * 2 blocks * 128 B
#define STAGE_BYTES (A_STAGE + B_STAGE)
#define GEMM_SMEM (GST * STAGE_BYTES) // 131072

__global__ __launch_bounds__(256, 1) void gemm_f16(
    const __half* __restrict__ A, const __half* __restrict__ B,
    float* __restrict__ C, int M, int N, int K)
{
    extern __shared__ char smem[];
    const uint32_t sb = smem_u32(smem);
    const int tid  = threadIdx.x;
    const int lane = tid & 31;
    const int wid  = tid >> 5;
    const int mt   = blockIdx.y * GBM;
    const int nt   = blockIdx.x * GBN;
    const int wm   = (wid >> 2) * 64;   // warp tile 64 x 32
    const int wn   = (wid & 3) * 32;
    const int NK   = K / GBK;

    float acc[4][4][4];
#pragma unroll
    for (int i = 0; i < 4; i++)
#pragma unroll
        for (int j = 0; j < 4; j++)
#pragma unroll
            for (int c = 0; c < 4; c++) acc[i][j][c] = 0.f;

    // ---- async stage loader ----
    auto load_stage = [&](int kt, int s) {
        const uint32_t as = sb + s * STAGE_BYTES;
        const uint32_t bs = as + A_STAGE;
        const __half* Ag = A + (size_t)mt * K + kt * GBK;
        const __half* Bg = B + (size_t)(kt * GBK) * N + nt;
#pragma unroll
        for (int i = 0; i < 4; i++) {            // A: 1024 chunks of 16B
            int id = tid + i * 256;
            int r = id >> 3, c = id & 7;
            cp_async16(as + r * 128 + ((c ^ (r & 7)) << 4),
                       Ag + (size_t)r * K + c * 8);
        }
#pragma unroll
        for (int i = 0; i < 4; i++) {            // B: 1024 chunks of 16B
            int id = tid + i * 256;
            int r = id >> 4, c = id & 15;
            uint32_t dst = bs + (c >> 3) * 8192 + r * 128 + (((c & 7) ^ (r & 7)) << 4);
            cp_async16(dst, Bg + (size_t)r * N + c * 8);
        }
        CP_COMMIT();
    };

    for (int s = 0; s < GST - 1; s++) load_stage(s, s);

    const int lr = lane & 15;      // ldmatrix row select
    const int lq = lane >> 4;      // ldmatrix col-half select

    for (int kt = 0; kt < NK; kt++) {
        CP_WAIT(2);
        __syncthreads();
        if (kt + GST - 1 < NK) load_stage(kt + GST - 1, (kt + GST - 1) & (GST - 1));

        const uint32_t as = sb + (kt & (GST - 1)) * STAGE_BYTES;
        const uint32_t bs = as + A_STAGE;

#pragma unroll
        for (int ks = 0; ks < 4; ks++) {
            const int kk = ks * 16;
            uint32_t ar[4][4];
#pragma unroll
            for (int mf = 0; mf < 4; mf++) {
                int r = wm + mf * 16 + lr;
                uint32_t addr = as + r * 128 + ((((kk >> 3) + lq) ^ (r & 7)) << 4);
                LDSM_X4(ar[mf], addr);
            }
            uint32_t br[2][4];
#pragma unroll
            for (int nf = 0; nf < 2; nf++) {
                int n0 = wn + nf * 16;
                int r  = kk + lr;
                int cc = ((n0 & 63) >> 3) + lq;
                uint32_t addr = bs + ((n0 >= 64) ? 8192 : 0) + r * 128 +
                                ((cc ^ (r & 7)) << 4);
                LDSM_X4_T(br[nf], addr);
            }
#pragma unroll
            for (int mf = 0; mf < 4; mf++)
#pragma unroll
                for (int nf = 0; nf < 4; nf++) {
                    uint32_t b0 = br[nf >> 1][(nf & 1) * 2];
                    uint32_t b1 = br[nf >> 1][(nf & 1) * 2 + 1];
                    MMA16816(acc[mf][nf], ar[mf], b0, b1);
                }
        }
    }

    // ---- epilogue: fp32 C ----
    const int gid = lane >> 2;
    const int tig = lane & 3;
#pragma unroll
    for (int mf = 0; mf < 4; mf++) {
        int row0 = mt + wm + mf * 16 + gid;
#pragma unroll
        for (int nf = 0; nf < 4; nf++) {
            int col = nt + wn + nf * 8 + tig * 2;
            *(float2*)(C + (size_t)row0 * N + col) =
                make_float2(acc[mf][nf][0], acc[mf][nf][1]);
            *(float2*)(C + (size_t)(row0 + 8) * N + col) =
                make_float2(acc[mf][nf][2], acc[mf][nf][3]);
        }
    }
}

// ---------------- fp32 -> fp16 convert (8 elems/thread) --------------------
__global__ void f2h_kernel(const float* __restrict__ in,
                           __half* __restrict__ out, int n8)
{
    int i = blockIdx.x * blockDim.x + threadIdx.x;
    if (i >= n8) return;
    float4 v0 = ((const float4*)in)[2 * i];
    float4 v1 = ((const float4*)in)[2 * i + 1];
    union { uint4 u; __half2 h[4]; } r;
    r.h[0] = __floats2half2_rn(v0.x, v0.y);
    r.h[1] = __floats2half2_rn(v0.z, v0.w);
    r.h[2] = __floats2half2_rn(v1.x, v1.y);
    r.h[3] = __floats2half2_rn(v1.z, v1.w);
    ((uint4*)out)[i] = r.u;
}

// ---------------- RoPE -----------------------------------------------------
__global__ void rope_kernel(float* __restrict__ t,
                            const float* __restrict__ cosb,
                            const float* __restrict__ sinb,
                            int nheads, int seq, int total)
{
    int idx = blockIdx.x * blockDim.x + threadIdx.x;
    if (idx >= total) return;
    int i = idx & 63;
    int s = ((idx >> 6) / nheads) % seq;
    float2* p = (float2*)t + idx;
    float2 v = *p;
    float c  = cosb[s * 64 + i];
    float sn = sinb[s * 64 + i];
    *p = make_float2(v.x * c - v.y * sn, v.x * sn + v.y * c);
}

// ---------------- flash attention (fp32 SIMT), fp16 output -----------------
#define QS_STRIDE 132
#define S_STRIDE  68

__global__ __launch_bounds__(256, 1) void flash_attn(
    const float* __restrict__ Qg, const float* __restrict__ Kg,
    const float* __restrict__ Vg, __half* __restrict__ Og, int seq)
{
    extern __shared__ float sm[];
    float* Qs   = sm;
    float* Ks4  = Qs  + 64 * QS_STRIDE;
    float* Vs   = Ks4 + 64 * 128;
    float* S    = Vs  + 64 * 128;
    float* mrow = S   + 64 * S_STRIDE;
    float* lrow = mrow + 64;
    float* crow = lrow + 64;

    const int qt  = blockIdx.x;
    const int h   = blockIdx.y;
    const int b   = blockIdx.z;
    const int kvh = h >> 2;
    const int tid = threadIdx.x;
    const int tx  = tid & 15;
    const int ty  = tid >> 4;
    const float scale = 0.08838834764831845f;

    const float* Qbase = Qg + ((size_t)b * seq) * (NH  * HD) + h   * HD;
    const float* Kbase = Kg + ((size_t)b * seq) * (NKV * HD) + kvh * HD;
    const float* Vbase = Vg + ((size_t)b * seq) * (NKV * HD) + kvh * HD;

#pragma unroll
    for (int i = 0; i < 8; i++) {
        int id = tid + i * 256;
        int r = id >> 5, f = id & 31;
        float4 v = *(const float4*)(Qbase + (size_t)(qt * 64 + r) * (NH * HD) + f * 4);
        *(float4*)(Qs + r * QS_STRIDE + f * 4) = v;
    }
    if (tid < 64) { mrow[tid] = -INFINITY; lrow[tid] = 0.f; }

    float o[4][8];
#pragma unroll
    for (int i = 0; i < 4; i++)
#pragma unroll
        for (int j = 0; j < 8; j++) o[i][j] = 0.f;

    __syncthreads();

    for (int kt = 0; kt <= qt; kt++) {
#pragma unroll
        for (int i = 0; i < 8; i++) {
            int id = tid + i * 256;
            int r = id >> 5, f = id & 31;
            size_t grow = (size_t)(kt * 64 + r) * (NKV * HD);
            float4 kv = *(const float4*)(Kbase + grow + f * 4);
            *(float4*)(Ks4 + r * 128 + ((f ^ (r & 31)) << 2)) = kv;
            float4 vv = *(const float4*)(Vbase + grow + f * 4);
            *(float4*)(Vs + r * 128 + f * 4) = vv;
        }
        __syncthreads();

        float acc[4][4];
#pragma unroll
        for (int i = 0; i < 4; i++)
#pragma unroll
            for (int j = 0; j < 4; j++) acc[i][j] = 0.f;

#pragma unroll 4
        for (int f = 0; f < 32; f++) {
            float4 qv[4], kv[4];
#pragma unroll
            for (int i = 0; i < 4; i++)
                qv[i] = *(const float4*)(Qs + (ty * 4 + i) * QS_STRIDE + f * 4);
#pragma unroll
            for (int j = 0; j < 4; j++) {
                int c = tx * 4 + j;
                kv[j] = *(const float4*)(Ks4 + c * 128 + ((f ^ (c & 31)) << 2));
            }
#pragma unroll
            for (int i = 0; i < 4; i++)
#pragma unroll
                for (int j = 0; j < 4; j++)
                    acc[i][j] += qv[i].x * kv[j].x + qv[i].y * kv[j].y +
                                 qv[i].z * kv[j].z + qv[i].w * kv[j].w;
        }

        const int q0 = qt * 64, k0 = kt * 64;
#pragma unroll
        for (int i = 0; i < 4; i++) {
            int qg = q0 + ty * 4 + i;
            int kc = k0 + tx * 4;
            float4 sv;
            sv.x = (kc + 0 > qg) ? -1e9f : acc[i][0] * scale;
            sv.y = (kc + 1 > qg) ? -1e9f : acc[i][1] * scale;
            sv.z = (kc + 2 > qg) ? -1e9f : acc[i][2] * scale;
            sv.w = (kc + 3 > qg) ? -1e9f : acc[i][3] * scale;
            *(float4*)(S + (ty * 4 + i) * S_STRIDE + tx * 4) = sv;
        }
        __syncthreads();

        if (tid < 64) {
            float* srow = S + tid * S_STRIDE;
            float mold = mrow[tid];
            float mx = mold;
#pragma unroll 8
            for (int c = 0; c < 64; c++) mx = fmaxf(mx, srow[c]);
            float corr = __expf(mold - mx);
            float lsum = 0.f;
#pragma unroll 8
            for (int c = 0; c < 64; c++) {
                float p = __expf(srow[c] - mx);
                srow[c] = p;
                lsum += p;
            }
            mrow[tid] = mx;
            lrow[tid] = lrow[tid] * corr + lsum;
            crow[tid] = corr;
        }
        __syncthreads();

        float cr[4];
#pragma unroll
        for (int i = 0; i < 4; i++) cr[i] = crow[ty * 4 + i];
#pragma unroll
        for (int i = 0; i < 4; i++)
#pragma unroll
            for (int j = 0; j < 8; j++) o[i][j] *= cr[i];

#pragma unroll 2
        for (int k = 0; k < 64; k++) {
            float pv[4];
#pragma unroll
            for (int i = 0; i < 4; i++) pv[i] = S[(ty * 4 + i) * S_STRIDE + k];
            float4 va = *(const float4*)(Vs + k * 128 + tx * 4);
            float4 vb = *(const float4*)(Vs + k * 128 + 64 + tx * 4);
#pragma unroll
            for (int i = 0; i < 4; i++) {
                o[i][0] += pv[i] * va.x;  o[i][1] += pv[i] * va.y;
                o[i][2] += pv[i] * va.z;  o[i][3] += pv[i] * va.w;
                o[i][4] += pv[i] * vb.x;  o[i][5] += pv[i] * vb.y;
                o[i][6] += pv[i] * vb.z;  o[i][7] += pv[i] * vb.w;
            }
        }
        __syncthreads();
    }

    // Epilogue: divide by l, write fp16 (b, s, h, d)
#pragma unroll
    for (int i = 0; i < 4; i++) {
        float linv = 1.0f / lrow[ty * 4 + i];
        size_t orow = ((size_t)b * seq + qt * 64 + ty * 4 + i) * (NH * HD) + h * HD;
        __half2* op = (__half2*)(Og + orow);
        op[tx * 2]          = __floats2half2_rn(o[0 * 0 + i][0] * linv, o[i][1] * linv);
        op[tx * 2 + 1]      = __floats2half2_rn(o[i][2] * linv, o[i][3] * linv);
        op[32 + tx * 2]     = __floats2half2_rn(o[i][4] * linv, o[i][5] * linv);
        op[32 + tx * 2 + 1] = __floats2half2_rn(o[i][6] * linv, o[i][7] * linv);
    }
}

// ---------------- host side ------------------------------------------------
extern "C" void kernel_launch(void* const* d_in, const int* in_sizes, int n_in,
                              void* d_out, int out_size)
{
    const float* x  = (const float*)d_in[0];
    const float* wq = (const float*)d_in[1];
    const float* wk = (const float*)d_in[2];
    const float* wv = (const float*)d_in[3];
    const float* wo = (const float*)d_in[4];
    const float* fc = (const float*)d_in[7];
    const float* fs = (const float*)d_in[8];
    float* out = (float*)d_out;

    float  *q, *k, *v;
    __half *xh, *wqh, *wkh, *wvh, *woh, *attnh;
    cudaGetSymbolAddress((void**)&q,     g_q);
    cudaGetSymbolAddress((void**)&k,     g_k);
    cudaGetSymbolAddress((void**)&v,     g_v);
    cudaGetSymbolAddress((void**)&xh,    g_xh);
    cudaGetSymbolAddress((void**)&wqh,   g_wqh);
    cudaGetSymbolAddress((void**)&wkh,   g_wkh);
    cudaGetSymbolAddress((void**)&wvh,   g_wvh);
    cudaGetSymbolAddress((void**)&woh,   g_woh);
    cudaGetSymbolAddress((void**)&attnh, g_attnh);

    const int M = MTOT;

    // fp32 -> fp16 converts
    f2h_kernel<<<(M * DIMM / 8 + 255) / 256, 256>>>(x,  xh,  M * DIMM / 8);
    f2h_kernel<<<(DIMM * NH * HD / 8 + 255) / 256, 256>>>(wq, wqh, DIMM * NH * HD / 8);
    f2h_kernel<<<(DIMM * NKV * HD / 8 + 255) / 256, 256>>>(wk, wkh, DIMM * NKV * HD / 8);
    f2h_kernel<<<(DIMM * NKV * HD / 8 + 255) / 256, 256>>>(wv, wvh, DIMM * NKV * HD / 8);
    f2h_kernel<<<(DIMM * DIMM / 8 + 255) / 256, 256>>>(wo, woh, DIMM * DIMM / 8);

    cudaFuncSetAttribute(gemm_f16, cudaFuncAttributeMaxDynamicSharedMemorySize,
                         GEMM_SMEM);

    // QKV projections (tensor cores via mma.sync)
    gemm_f16<<<dim3(NH * HD / GBN,  M / GBM), 256, GEMM_SMEM>>>(xh, wqh, q, M, NH * HD,  DIMM);
    gemm_f16<<<dim3(NKV * HD / GBN, M / GBM), 256, GEMM_SMEM>>>(xh, wkh, k, M, NKV * HD, DIMM);
    gemm_f16<<<dim3(NKV * HD / GBN, M / GBM), 256, GEMM_SMEM>>>(xh, wvh, v, M, NKV * HD, DIMM);

    // RoPE
    int qpairs = M * NH  * 64;
    int kpairs = M * NKV * 64;
    rope_kernel<<<(qpairs + 255) / 256, 256>>>(q, fc, fs, NH,  SEQL, qpairs);
    rope_kernel<<<(kpairs + 255) / 256, 256>>>(k, fc, fs, NKV, SEQL, kpairs);

    // Flash attention (fp32, fp16 output)
    const int fa_smem = (64 * QS_STRIDE + 64 * 128 + 64 * 128 +
                         64 * S_STRIDE + 192) * sizeof(float);
    cudaFuncSetAttribute(flash_attn, cudaFuncAttributeMaxDynamicSharedMemorySize, fa_smem);
    flash_attn<<<dim3(SEQL / 64, NH, BSZ), 256, fa_smem>>>(q, k, v, attnh, SEQL);

    // Output projection
    gemm_f16<<<dim3(DIMM / GBN, M / GBM), 256, GEMM_SMEM>>>(attnh, woh, out, M, DIMM, DIMM);
}

// round 4
// speedup vs baseline: 8.1494x; 3.3801x over previous
#include <cuda_runtime.h>
#include <cuda_fp16.h>
#include <math.h>
#include <stdint.h>

#define BSZ  2
#define SEQL 2048
#define DIMM 4096
#define NH   32
#define NKV  8
#define HD   128
#define MTOT (BSZ * SEQL)          // 4096

// ---------------- scratch (__device__ globals) ----------------------------
__device__ float  g_q[MTOT * NH * HD];
__device__ float  g_k[MTOT * NKV * HD];
__device__ float  g_v[MTOT * NKV * HD];
__device__ __half g_xh[MTOT * DIMM];
__device__ __half g_wqh[DIMM * NH * HD];
__device__ __half g_wkh[DIMM * NKV * HD];
__device__ __half g_wvh[DIMM * NKV * HD];
__device__ __half g_woh[DIMM * DIMM];
__device__ __half g_attnh[MTOT * NH * HD];
__device__ __half g_qh[MTOT * NH * HD];
__device__ __half g_kh[MTOT * NKV * HD];
__device__ __half g_vh[MTOT * NKV * HD];

// ---------------- PTX helpers ---------------------------------------------
__device__ __forceinline__ uint32_t smem_u32(const void* p) {
    uint32_t a;
    asm("{ .reg .u64 t; cvta.to.shared.u64 t, %1; cvt.u32.u64 %0, t; }"
        : "=r"(a) : "l"(p));
    return a;
}
__device__ __forceinline__ void cp_async16(uint32_t dst, const void* src) {
    asm volatile("cp.async.cg.shared.global [%0], [%1], 16;" :: "r"(dst), "l"(src));
}
#define CP_COMMIT() asm volatile("cp.async.commit_group;" ::: "memory")
#define CP_WAIT(n)  asm volatile("cp.async.wait_group %0;" :: "n"(n) : "memory")

#define LDSM_X4(R, addr) \
    asm volatile("ldmatrix.sync.aligned.m8n8.x4.shared.b16 {%0,%1,%2,%3}, [%4];" \
        : "=r"((R)[0]), "=r"((R)[1]), "=r"((R)[2]), "=r"((R)[3]) : "r"(addr))
#define LDSM_X4_T(R, addr) \
    asm volatile("ldmatrix.sync.aligned.m8n8.x4.trans.shared.b16 {%0,%1,%2,%3}, [%4];" \
        : "=r"((R)[0]), "=r"((R)[1]), "=r"((R)[2]), "=r"((R)[3]) : "r"(addr))

#define MMA16816(D, A, B0, B1) \
    asm volatile("mma.sync.aligned.m16n8k16.row.col.f32.f16.f16.f32 " \
        "{%0,%1,%2,%3}, {%4,%5,%6,%7}, {%8,%9}, {%0,%1,%2,%3};" \
        : "+f"((D)[0]), "+f"((D)[1]), "+f"((D)[2]), "+f"((D)[3]) \
        : "r"((A)[0]), "r"((A)[1]), "r"((A)[2]), "r"((A)[3]), "r"(B0), "r"(B1))

// ---------------- fp16 mma.sync GEMM: C[M,N] = A[M,K] @ B[K,N] -------------
#define GBM 128
#define GBN 128
#define GBK 64
#define GST 4
#define A_STAGE 16384
#define B_STAGE 16384
#define STAGE_BYTES (A_STAGE + B_STAGE)
#define GEMM_SMEM (GST * STAGE_BYTES)

__global__ __launch_bounds__(256, 1) void gemm_f16(
    const __half* __restrict__ A, const __half* __restrict__ B,
    float* __restrict__ C, int M, int N, int K)
{
    extern __shared__ char smem[];
    const uint32_t sb = smem_u32(smem);
    const int tid  = threadIdx.x;
    const int lane = tid & 31;
    const int wid  = tid >> 5;
    const int mt   = blockIdx.y * GBM;
    const int nt   = blockIdx.x * GBN;
    const int wm   = (wid >> 2) * 64;
    const int wn   = (wid & 3) * 32;
    const int NK   = K / GBK;

    float acc[4][4][4];
#pragma unroll
    for (int i = 0; i < 4; i++)
#pragma unroll
        for (int j = 0; j < 4; j++)
#pragma unroll
            for (int c = 0; c < 4; c++) acc[i][j][c] = 0.f;

    auto load_stage = [&](int kt, int s) {
        const uint32_t as = sb + s * STAGE_BYTES;
        const uint32_t bs = as + A_STAGE;
        const __half* Ag = A + (size_t)mt * K + kt * GBK;
        const __half* Bg = B + (size_t)(kt * GBK) * N + nt;
#pragma unroll
        for (int i = 0; i < 4; i++) {
            int id = tid + i * 256;
            int r = id >> 3, c = id & 7;
            cp_async16(as + r * 128 + ((c ^ (r & 7)) << 4),
                       Ag + (size_t)r * K + c * 8);
        }
#pragma unroll
        for (int i = 0; i < 4; i++) {
            int id = tid + i * 256;
            int r = id >> 4, c = id & 15;
            uint32_t dst = bs + (c >> 3) * 8192 + r * 128 + (((c & 7) ^ (r & 7)) << 4);
            cp_async16(dst, Bg + (size_t)r * N + c * 8);
        }
        CP_COMMIT();
    };

    for (int s = 0; s < GST - 1; s++) load_stage(s, s);

    const int lr = lane & 15;
    const int lq = lane >> 4;

    for (int kt = 0; kt < NK; kt++) {
        CP_WAIT(2);
        __syncthreads();
        if (kt + GST - 1 < NK) load_stage(kt + GST - 1, (kt + GST - 1) & (GST - 1));

        const uint32_t as = sb + (kt & (GST - 1)) * STAGE_BYTES;
        const uint32_t bs = as + A_STAGE;

#pragma unroll
        for (int ks = 0; ks < 4; ks++) {
            const int kk = ks * 16;
            uint32_t ar[4][4];
#pragma unroll
            for (int mf = 0; mf < 4; mf++) {
                int r = wm + mf * 16 + lr;
                uint32_t addr = as + r * 128 + ((((kk >> 3) + lq) ^ (r & 7)) << 4);
                LDSM_X4(ar[mf], addr);
            }
            uint32_t br[2][4];
#pragma unroll
            for (int nf = 0; nf < 2; nf++) {
                int n0 = wn + nf * 16;
                int r  = kk + lr;
                int cc = ((n0 & 63) >> 3) + lq;
                uint32_t addr = bs + ((n0 >= 64) ? 8192 : 0) + r * 128 +
                                ((cc ^ (r & 7)) << 4);
                LDSM_X4_T(br[nf], addr);
            }
#pragma unroll
            for (int mf = 0; mf < 4; mf++)
#pragma unroll
                for (int nf = 0; nf < 4; nf++) {
                    uint32_t b0 = br[nf >> 1][(nf & 1) * 2];
                    uint32_t b1 = br[nf >> 1][(nf & 1) * 2 + 1];
                    MMA16816(acc[mf][nf], ar[mf], b0, b1);
                }
        }
    }

    const int gid = lane >> 2;
    const int tig = lane & 3;
#pragma unroll
    for (int mf = 0; mf < 4; mf++) {
        int row0 = mt + wm + mf * 16 + gid;
#pragma unroll
        for (int nf = 0; nf < 4; nf++) {
            int col = nt + wn + nf * 8 + tig * 2;
            *(float2*)(C + (size_t)row0 * N + col) =
                make_float2(acc[mf][nf][0], acc[mf][nf][1]);
            *(float2*)(C + (size_t)(row0 + 8) * N + col) =
                make_float2(acc[mf][nf][2], acc[mf][nf][3]);
        }
    }
}

// ---------------- fp32 -> fp16 convert -------------------------------------
__global__ void f2h_kernel(const float* __restrict__ in,
                           __half* __restrict__ out, int n8)
{
    int i = blockIdx.x * blockDim.x + threadIdx.x;
    if (i >= n8) return;
    float4 v0 = ((const float4*)in)[2 * i];
    float4 v1 = ((const float4*)in)[2 * i + 1];
    union { uint4 u; __half2 h[4]; } r;
    r.h[0] = __floats2half2_rn(v0.x, v0.y);
    r.h[1] = __floats2half2_rn(v0.z, v0.w);
    r.h[2] = __floats2half2_rn(v1.x, v1.y);
    r.h[3] = __floats2half2_rn(v1.z, v1.w);
    ((uint4*)out)[i] = r.u;
}

// ---------------- RoPE: fp32 in -> fp16 out --------------------------------
__global__ void rope_f16(const float* __restrict__ in, __half* __restrict__ out,
                         const float* __restrict__ cosb,
                         const float* __restrict__ sinb,
                         int nheads, int seq, int total)
{
    int idx = blockIdx.x * blockDim.x + threadIdx.x;
    if (idx >= total) return;
    int i = idx & 63;
    int s = ((idx >> 6) / nheads) % seq;
    float2 v = ((const float2*)in)[idx];
    float c  = cosb[s * 64 + i];
    float sn = sinb[s * 64 + i];
    ((__half2*)out)[idx] = __floats2half2_rn(v.x * c - v.y * sn,
                                             v.x * sn + v.y * c);
}

// ---------------- fp16 tensor-core flash attention -------------------------
// CTA: 128 q-rows, 8 warps (16 rows each), 64-key tiles, double-buffered K/V.
#define FQ 128
#define FK 64
#define QBYTES   (FQ * 256)            // 32768
#define KVSTAGE  (FK * 256 * 2)        // 32768 (K 16KB + V 16KB)
#define FA_SMEM  (QBYTES + 2 * KVSTAGE)

__device__ __forceinline__ uint32_t swz(uint32_t c, uint32_t r) {
    return ((c ^ (r & 7)) & 7) | (c & 8);
}

__global__ __launch_bounds__(256, 1) void flash_f16(
    const __half* __restrict__ Qh, const __half* __restrict__ Kh,
    const __half* __restrict__ Vh, __half* __restrict__ Oh, int seq)
{
    extern __shared__ char smc[];
    const uint32_t sb = smem_u32(smc);
    const uint32_t Qs = sb;

    const int qt = blockIdx.x, h = blockIdx.y, b = blockIdx.z;
    const int kvh = h >> 2;
    const int tid = threadIdx.x, lane = tid & 31, wid = tid >> 5;
    const int lr = lane & 15, lq = lane >> 4;
    const int g = lane >> 2, tq = lane & 3;
    const float scale = 0.08838834764831845f;

    const __half* Qg = Qh + ((size_t)(b * seq + qt * FQ) * NH + h) * HD;
    const __half* Kg = Kh + ((size_t)b * seq * NKV + kvh) * HD;
    const __half* Vg = Vh + ((size_t)b * seq * NKV + kvh) * HD;

    // Q tile: 128 rows x 16 chunks
#pragma unroll
    for (int i = 0; i < 8; i++) {
        int id = tid + i * 256;
        int r = id >> 4, c = id & 15;
        cp_async16(Qs + r * 256 + swz(c, r) * 16, Qg + (size_t)r * (NH * HD) + c * 8);
    }
    CP_COMMIT();

    auto load_kv = [&](int kt, int s) {
        uint32_t ks = sb + QBYTES + s * KVSTAGE;
        uint32_t vs = ks + FK * 256;
        const __half* kg = Kg + (size_t)(kt * FK) * (NKV * HD);
        const __half* vg = Vg + (size_t)(kt * FK) * (NKV * HD);
#pragma unroll
        for (int i = 0; i < 4; i++) {
            int id = tid + i * 256;
            int r = id >> 4, c = id & 15;
            uint32_t off = r * 256 + swz(c, r) * 16;
            cp_async16(ks + off, kg + (size_t)r * (NKV * HD) + c * 8);
            cp_async16(vs + off, vg + (size_t)r * (NKV * HD) + c * 8);
        }
        CP_COMMIT();
    };

    const int ntiles = 2 * qt + 2;
    load_kv(0, 0);

    float acc_o[16][4];
#pragma unroll
    for (int d = 0; d < 16; d++)
#pragma unroll
        for (int c = 0; c < 4; c++) acc_o[d][c] = 0.f;
    float mrow[2] = {-1e30f, -1e30f};
    float lrow[2] = {0.f, 0.f};

    const int row0 = qt * FQ + wid * 16 + g;   // rows row0, row0+8

    for (int kt = 0; kt < ntiles; kt++) {
        if (kt + 1 < ntiles) { load_kv(kt + 1, (kt + 1) & 1); CP_WAIT(1); }
        else                 { CP_WAIT(0); }
        __syncthreads();

        const uint32_t ks = sb + QBYTES + (kt & 1) * KVSTAGE;
        const uint32_t vs = ks + FK * 256;

        // ---- S = Q @ K^T  (warp tile 16 x 64) ----
        float accs[8][4];
#pragma unroll
        for (int j = 0; j < 8; j++)
#pragma unroll
            for (int c = 0; c < 4; c++) accs[j][c] = 0.f;

#pragma unroll
        for (int d = 0; d < 8; d++) {
            uint32_t a[4];
            {
                int r = wid * 16 + lr;
                LDSM_X4(a, Qs + r * 256 + swz(d * 2 + lq, r) * 16);
            }
#pragma unroll
            for (int n = 0; n < 4; n++) {
                uint32_t kb[4];
                int r = n * 16 + lr;
                LDSM_X4(kb, ks + r * 256 + swz(d * 2 + lq, r) * 16);
                MMA16816(accs[n * 2],     a, kb[0], kb[2]);
                MMA16816(accs[n * 2 + 1], a, kb[1], kb[3]);
            }
        }

        // ---- online softmax (registers, quad-reduced) ----
        const bool need_mask = (kt >= 2 * qt);
#pragma unroll
        for (int rr = 0; rr < 2; rr++) {
            const int grow = row0 + rr * 8;
            float mx = mrow[rr];
#pragma unroll
            for (int j = 0; j < 8; j++) {
                float s0 = accs[j][rr * 2] * scale;
                float s1 = accs[j][rr * 2 + 1] * scale;
                if (need_mask) {
                    int c0 = kt * FK + j * 8 + tq * 2;
                    if (c0 > grow)     s0 = -1e30f;
                    if (c0 + 1 > grow) s1 = -1e30f;
                }
                accs[j][rr * 2]     = s0;
                accs[j][rr * 2 + 1] = s1;
                mx = fmaxf(mx, fmaxf(s0, s1));
            }
            mx = fmaxf(mx, __shfl_xor_sync(0xFFFFFFFFu, mx, 1));
            mx = fmaxf(mx, __shfl_xor_sync(0xFFFFFFFFu, mx, 2));
            float corr = __expf(mrow[rr] - mx);
            mrow[rr] = mx;
            float ls = 0.f;
#pragma unroll
            for (int j = 0; j < 8; j++) {
                float p0 = __expf(accs[j][rr * 2] - mx);
                float p1 = __expf(accs[j][rr * 2 + 1] - mx);
                accs[j][rr * 2]     = p0;
                accs[j][rr * 2 + 1] = p1;
                ls += p0 + p1;
            }
            ls += __shfl_xor_sync(0xFFFFFFFFu, ls, 1);
            ls += __shfl_xor_sync(0xFFFFFFFFu, ls, 2);
            lrow[rr] = lrow[rr] * corr + ls;
#pragma unroll
            for (int d = 0; d < 16; d++) {
                acc_o[d][rr * 2]     *= corr;
                acc_o[d][rr * 2 + 1] *= corr;
            }
        }

        // ---- P (fp16, C-frag == A-frag identity) ----
        uint32_t p[8][2];
#pragma unroll
        for (int j = 0; j < 8; j++) {
            __half2 h0 = __floats2half2_rn(accs[j][0], accs[j][1]);
            __half2 h1 = __floats2half2_rn(accs[j][2], accs[j][3]);
            p[j][0] = *(uint32_t*)&h0;
            p[j][1] = *(uint32_t*)&h1;
        }

        // ---- O += P @ V ----
#pragma unroll
        for (int kk = 0; kk < 4; kk++) {
            uint32_t a[4] = {p[kk * 2][0], p[kk * 2][1],
                             p[kk * 2 + 1][0], p[kk * 2 + 1][1]};
#pragma unroll
            for (int dn = 0; dn < 8; dn++) {
                uint32_t vb[4];
                int r = kk * 16 + lr;
                LDSM_X4_T(vb, vs + r * 256 + swz(dn * 2 + lq, r) * 16);
                MMA16816(acc_o[dn * 2],     a, vb[0], vb[1]);
                MMA16816(acc_o[dn * 2 + 1], a, vb[2], vb[3]);
            }
        }
        __syncthreads();
    }

    // ---- epilogue ----
    const float il0 = 1.f / lrow[0];
    const float il1 = 1.f / lrow[1];
    __half* Og = Oh + ((size_t)(b * seq + row0) * NH + h) * HD;
#pragma unroll
    for (int dn = 0; dn < 16; dn++) {
        int d = dn * 8 + tq * 2;
        *(__half2*)(Og + d) =
            __floats2half2_rn(acc_o[dn][0] * il0, acc_o[dn][1] * il0);
        *(__half2*)(Og + (size_t)8 * (NH * HD) + d) =
            __floats2half2_rn(acc_o[dn][2] * il1, acc_o[dn][3] * il1);
    }
}

// ---------------- host side ------------------------------------------------
extern "C" void kernel_launch(void* const* d_in, const int* in_sizes, int n_in,
                              void* d_out, int out_size)
{
    const float* x  = (const float*)d_in[0];
    const float* wq = (const float*)d_in[1];
    const float* wk = (const float*)d_in[2];
    const float* wv = (const float*)d_in[3];
    const float* wo = (const float*)d_in[4];
    const float* fc = (const float*)d_in[7];
    const float* fs = (const float*)d_in[8];
    float* out = (float*)d_out;

    float  *q, *k, *v;
    __half *xh, *wqh, *wkh, *wvh, *woh, *attnh, *qh, *kh, *vh;
    cudaGetSymbolAddress((void**)&q,     g_q);
    cudaGetSymbolAddress((void**)&k,     g_k);
    cudaGetSymbolAddress((void**)&v,     g_v);
    cudaGetSymbolAddress((void**)&xh,    g_xh);
    cudaGetSymbolAddress((void**)&wqh,   g_wqh);
    cudaGetSymbolAddress((void**)&wkh,   g_wkh);
    cudaGetSymbolAddress((void**)&wvh,   g_wvh);
    cudaGetSymbolAddress((void**)&woh,   g_woh);
    cudaGetSymbolAddress((void**)&attnh, g_attnh);
    cudaGetSymbolAddress((void**)&qh,    g_qh);
    cudaGetSymbolAddress((void**)&kh,    g_kh);
    cudaGetSymbolAddress((void**)&vh,    g_vh);

    const int M = MTOT;

    f2h_kernel<<<(M * DIMM / 8 + 255) / 256, 256>>>(x,  xh,  M * DIMM / 8);
    f2h_kernel<<<(DIMM * NH * HD / 8 + 255) / 256, 256>>>(wq, wqh, DIMM * NH * HD / 8);
    f2h_kernel<<<(DIMM * NKV * HD / 8 + 255) / 256, 256>>>(wk, wkh, DIMM * NKV * HD / 8);
    f2h_kernel<<<(DIMM * NKV * HD / 8 + 255) / 256, 256>>>(wv, wvh, DIMM * NKV * HD / 8);
    f2h_kernel<<<(DIMM * DIMM / 8 + 255) / 256, 256>>>(wo, woh, DIMM * DIMM / 8);

    cudaFuncSetAttribute(gemm_f16, cudaFuncAttributeMaxDynamicSharedMemorySize,
                         GEMM_SMEM);

    gemm_f16<<<dim3(NH * HD / GBN,  M / GBM), 256, GEMM_SMEM>>>(xh, wqh, q, M, NH * HD,  DIMM);
    gemm_f16<<<dim3(NKV * HD / GBN, M / GBM), 256, GEMM_SMEM>>>(xh, wkh, k, M, NKV * HD, DIMM);
    gemm_f16<<<dim3(NKV * HD / GBN, M / GBM), 256, GEMM_SMEM>>>(xh, wvh, v, M, NKV * HD, DIMM);

    // RoPE -> fp16 Q/K ; V -> fp16
    int qpairs = M * NH  * 64;
    int kpairs = M * NKV * 64;
    rope_f16<<<(qpairs + 255) / 256, 256>>>(q, qh, fc, fs, NH,  SEQL, qpairs);
    rope_f16<<<(kpairs + 255) / 256, 256>>>(k, kh, fc, fs, NKV, SEQL, kpairs);
    f2h_kernel<<<(M * NKV * HD / 8 + 255) / 256, 256>>>(v, vh, M * NKV * HD / 8);

    // fp16 tensor-core flash attention
    cudaFuncSetAttribute(flash_f16, cudaFuncAttributeMaxDynamicSharedMemorySize,
                         FA_SMEM);
    flash_f16<<<dim3(SEQL / FQ, NH, BSZ), 256, FA_SMEM>>>(qh, kh, vh, attnh, SEQL);

    // Output projection
    gemm_f16<<<dim3(DIMM / GBN, M / GBM), 256, GEMM_SMEM>>>(attnh, woh, out, M, DIMM, DIMM);
}

// round 5
// speedup vs baseline: 8.3668x; 1.0267x over previous
#include <cuda_runtime.h>
#include <cuda_fp16.h>
#include <math.h>
#include <stdint.h>

#define BSZ  2
#define SEQL 2048
#define DIMM 4096
#define NH   32
#define NKV  8
#define HD   128
#define MTOT (BSZ * SEQL)          // 4096
#define NQKV (NH * HD + 2 * NKV * HD)   // 6144

// ---------------- scratch (__device__ globals) ----------------------------
__device__ __half g_xh[MTOT * DIMM];
__device__ __half g_wqkvh[DIMM * NQKV];
__device__ __half g_woh[DIMM * DIMM];
__device__ __half g_attnh[MTOT * NH * HD];
__device__ __half g_qh[MTOT * NH * HD];
__device__ __half g_kh[MTOT * NKV * HD];
__device__ __half g_vh[MTOT * NKV * HD];

// ---------------- PTX helpers ---------------------------------------------
__device__ __forceinline__ uint32_t smem_u32(const void* p) {
    uint32_t a;
    asm("{ .reg .u64 t; cvta.to.shared.u64 t, %1; cvt.u32.u64 %0, t; }"
        : "=r"(a) : "l"(p));
    return a;
}
__device__ __forceinline__ void cp_async16(uint32_t dst, const void* src) {
    asm volatile("cp.async.cg.shared.global [%0], [%1], 16;" :: "r"(dst), "l"(src));
}
#define CP_COMMIT() asm volatile("cp.async.commit_group;" ::: "memory")
#define CP_WAIT(n)  asm volatile("cp.async.wait_group %0;" :: "n"(n) : "memory")

#define LDSM_X4(R, addr) \
    asm volatile("ldmatrix.sync.aligned.m8n8.x4.shared.b16 {%0,%1,%2,%3}, [%4];" \
        : "=r"((R)[0]), "=r"((R)[1]), "=r"((R)[2]), "=r"((R)[3]) : "r"(addr))
#define LDSM_X4_T(R, addr) \
    asm volatile("ldmatrix.sync.aligned.m8n8.x4.trans.shared.b16 {%0,%1,%2,%3}, [%4];" \
        : "=r"((R)[0]), "=r"((R)[1]), "=r"((R)[2]), "=r"((R)[3]) : "r"(addr))

#define MMA16816(D, A, B0, B1) \
    asm volatile("mma.sync.aligned.m16n8k16.row.col.f32.f16.f16.f32 " \
        "{%0,%1,%2,%3}, {%4,%5,%6,%7}, {%8,%9}, {%0,%1,%2,%3};" \
        : "+f"((D)[0]), "+f"((D)[1]), "+f"((D)[2]), "+f"((D)[3]) \
        : "r"((A)[0]), "r"((A)[1]), "r"((A)[2]), "r"((A)[3]), "r"(B0), "r"(B1))

// ---------------- fp16 mma.sync GEMM, 128x256 tile -------------------------
// MODE 0: C fp32 out. MODE 1: fused RoPE + fp16 split epilogue (q|k|v).
#define GBM 128
#define GBN 256
#define GBK 64
#define GST 4
#define A_STAGE 16384                      // 128 rows * 128 B
#define B_STAGE 32768                      // 64 rows * 4 blocks * 128 B
#define STAGE_BYTES (A_STAGE + B_STAGE)    // 49152
#define GEMM_SMEM (GST * STAGE_BYTES)      // 196608

template<int MODE>
__global__ __launch_bounds__(256, 1) void gemm_f16_256(
    const __half* __restrict__ A, const __half* __restrict__ B,
    float* __restrict__ C,
    __half* __restrict__ Qd, __half* __restrict__ Kd, __half* __restrict__ Vd,
    const float* __restrict__ cosb, const float* __restrict__ sinb,
    int M, int N, int K)
{
    extern __shared__ char smem[];
    const uint32_t sb = smem_u32(smem);
    const int tid  = threadIdx.x;
    const int lane = tid & 31;
    const int wid  = tid >> 5;
    const int mt   = blockIdx.y * GBM;
    const int nt   = blockIdx.x * GBN;
    const int wm   = (wid >> 2) * 64;      // 2x4 warp grid, 64x64 warp tile
    const int wn   = (wid & 3) * 64;
    const int NK   = K / GBK;

    float acc[4][8][4];
#pragma unroll
    for (int i = 0; i < 4; i++)
#pragma unroll
        for (int j = 0; j < 8; j++)
#pragma unroll
            for (int c = 0; c < 4; c++) acc[i][j][c] = 0.f;

    auto load_stage = [&](int kt, int s) {
        const uint32_t as = sb + s * STAGE_BYTES;
        const uint32_t bs = as + A_STAGE;
        const __half* Ag = A + (size_t)mt * K + kt * GBK;
        const __half* Bg = B + (size_t)(kt * GBK) * N + nt;
#pragma unroll
        for (int i = 0; i < 4; i++) {          // A: 1024 16B chunks
            int id = tid + i * 256;
            int r = id >> 3, c = id & 7;
            cp_async16(as + r * 128 + ((c ^ (r & 7)) << 4),
                       Ag + (size_t)r * K + c * 8);
        }
#pragma unroll
        for (int i = 0; i < 8; i++) {          // B: 2048 16B chunks
            int id = tid + i * 256;
            int r = id >> 5, c = id & 31;      // r 0..63, c 0..31
            uint32_t dst = bs + (c >> 3) * 8192 + r * 128 +
                           (((c & 7) ^ (r & 7)) << 4);
            cp_async16(dst, Bg + (size_t)r * N + c * 8);
        }
        CP_COMMIT();
    };

    for (int s = 0; s < GST - 1; s++) load_stage(s, s);

    const int lr = lane & 15;
    const int lq = lane >> 4;

    for (int kt = 0; kt < NK; kt++) {
        CP_WAIT(2);
        __syncthreads();
        if (kt + GST - 1 < NK) load_stage(kt + GST - 1, (kt + GST - 1) & (GST - 1));

        const uint32_t as = sb + (kt & (GST - 1)) * STAGE_BYTES;
        const uint32_t bs = as + A_STAGE;

#pragma unroll
        for (int ks = 0; ks < 4; ks++) {
            const int kk = ks * 16;
            uint32_t ar[4][4];
#pragma unroll
            for (int mf = 0; mf < 4; mf++) {
                int r = wm + mf * 16 + lr;
                LDSM_X4(ar[mf], as + r * 128 + ((((kk >> 3) + lq) ^ (r & 7)) << 4));
            }
            uint32_t br[4][4];
#pragma unroll
            for (int nf2 = 0; nf2 < 4; nf2++) {
                int n0 = wn + nf2 * 16;
                int r  = kk + lr;
                int cc = ((n0 & 63) >> 3) + lq;
                uint32_t addr = bs + (n0 >> 6) * 8192 + r * 128 +
                                ((cc ^ (r & 7)) << 4);
                LDSM_X4_T(br[nf2], addr);
            }
#pragma unroll
            for (int mf = 0; mf < 4; mf++)
#pragma unroll
                for (int nf = 0; nf < 8; nf++) {
                    uint32_t b0 = br[nf >> 1][(nf & 1) * 2];
                    uint32_t b1 = br[nf >> 1][(nf & 1) * 2 + 1];
                    MMA16816(acc[mf][nf], ar[mf], b0, b1);
                }
        }
    }

    const int g   = lane >> 2;
    const int tq  = lane & 3;

    if (MODE == 0) {
#pragma unroll
        for (int mf = 0; mf < 4; mf++) {
            int row0 = mt + wm + mf * 16 + g;
#pragma unroll
            for (int nf = 0; nf < 8; nf++) {
                int col = nt + wn + nf * 8 + tq * 2;
                *(float2*)(C + (size_t)row0 * N + col) =
                    make_float2(acc[mf][nf][0], acc[mf][nf][1]);
                *(float2*)(C + (size_t)(row0 + 8) * N + col) =
                    make_float2(acc[mf][nf][2], acc[mf][nf][3]);
            }
        }
    } else {
        // region: q cols [0,4096), k [4096,5120), v [5120,6144) — tile-aligned
        const int region = (nt >= 5 * 1024) ? 2 : (nt >= 4 * 1024 ? 1 : 0);
        __half* dst = region == 0 ? Qd : (region == 1 ? Kd : Vd);
        const int ld = region == 0 ? NH * HD : NKV * HD;
        const int cb = nt - (region == 0 ? 0 : (region == 1 ? 4096 : 5120));
        const bool dorope = (region < 2);
#pragma unroll
        for (int mf = 0; mf < 4; mf++) {
            int r0 = mt + wm + mf * 16 + g;
            int s0 = r0 & (SEQL - 1);
            int s1 = (r0 + 8) & (SEQL - 1);
#pragma unroll
            for (int nf = 0; nf < 8; nf++) {
                int colg = wn + nf * 8 + tq * 2;
                float a0 = acc[mf][nf][0], a1 = acc[mf][nf][1];
                float a2 = acc[mf][nf][2], a3 = acc[mf][nf][3];
                __half2 h0, h1;
                if (dorope) {
                    int i = ((nt + colg) & 127) >> 1;
                    float c0 = cosb[s0 * 64 + i], n0 = sinb[s0 * 64 + i];
                    float c1 = cosb[s1 * 64 + i], n1 = sinb[s1 * 64 + i];
                    h0 = __floats2half2_rn(a0 * c0 - a1 * n0, a0 * n0 + a1 * c0);
                    h1 = __floats2half2_rn(a2 * c1 - a3 * n1, a2 * n1 + a3 * c1);
                } else {
                    h0 = __floats2half2_rn(a0, a1);
                    h1 = __floats2half2_rn(a2, a3);
                }
                *(__half2*)(dst + (size_t)r0 * ld + cb + colg) = h0;
                *(__half2*)(dst + (size_t)(r0 + 8) * ld + cb + colg) = h1;
            }
        }
    }
}

// ---------------- fp32 -> fp16 converts ------------------------------------
__global__ void f2h_kernel(const float* __restrict__ in,
                           __half* __restrict__ out, int n8)
{
    int i = blockIdx.x * blockDim.x + threadIdx.x;
    if (i >= n8) return;
    float4 v0 = ((const float4*)in)[2 * i];
    float4 v1 = ((const float4*)in)[2 * i + 1];
    union { uint4 u; __half2 h[4]; } r;
    r.h[0] = __floats2half2_rn(v0.x, v0.y);
    r.h[1] = __floats2half2_rn(v0.z, v0.w);
    r.h[2] = __floats2half2_rn(v1.x, v1.y);
    r.h[3] = __floats2half2_rn(v1.z, v1.w);
    ((uint4*)out)[i] = r.u;
}

// in [R][C] fp32 -> out rows of width LD at column offset O (fp16)
__global__ void f2h_strided(const float* __restrict__ in,
                            __half* __restrict__ out,
                            int C8, int LD, int O, int n8)
{
    int i = blockIdx.x * blockDim.x + threadIdx.x;
    if (i >= n8) return;
    int r = i / C8, c = i % C8;
    float4 v0 = ((const float4*)in)[2 * i];
    float4 v1 = ((const float4*)in)[2 * i + 1];
    union { uint4 u; __half2 h[4]; } rr;
    rr.h[0] = __floats2half2_rn(v0.x, v0.y);
    rr.h[1] = __floats2half2_rn(v0.z, v0.w);
    rr.h[2] = __floats2half2_rn(v1.x, v1.y);
    rr.h[3] = __floats2half2_rn(v1.z, v1.w);
    *(uint4*)(out + (size_t)r * LD + O + c * 8) = rr.u;
}

// ---------------- fp16 tensor-core flash attention -------------------------
#define FQ 128
#define FK 64
#define QBYTES   (FQ * 256)
#define KVSTAGE  (FK * 256 * 2)
#define FA_SMEM  (QBYTES + 2 * KVSTAGE)

__device__ __forceinline__ uint32_t swz(uint32_t c, uint32_t r) {
    return ((c ^ (r & 7)) & 7) | (c & 8);
}

__global__ __launch_bounds__(256, 1) void flash_f16(
    const __half* __restrict__ Qh, const __half* __restrict__ Kh,
    const __half* __restrict__ Vh, __half* __restrict__ Oh, int seq)
{
    extern __shared__ char smc[];
    const uint32_t sb = smem_u32(smc);
    const uint32_t Qs = sb;

    const int qt = blockIdx.x, h = blockIdx.y, b = blockIdx.z;
    const int kvh = h >> 2;
    const int tid = threadIdx.x, lane = tid & 31, wid = tid >> 5;
    const int lr = lane & 15, lq = lane >> 4;
    const int g = lane >> 2, tq = lane & 3;
    const float scale = 0.08838834764831845f;

    const __half* Qg = Qh + ((size_t)(b * seq + qt * FQ) * NH + h) * HD;
    const __half* Kg = Kh + ((size_t)b * seq * NKV + kvh) * HD;
    const __half* Vg = Vh + ((size_t)b * seq * NKV + kvh) * HD;

#pragma unroll
    for (int i = 0; i < 8; i++) {
        int id = tid + i * 256;
        int r = id >> 4, c = id & 15;
        cp_async16(Qs + r * 256 + swz(c, r) * 16, Qg + (size_t)r * (NH * HD) + c * 8);
    }
    CP_COMMIT();

    auto load_kv = [&](int kt, int s) {
        uint32_t ks = sb + QBYTES + s * KVSTAGE;
        uint32_t vs = ks + FK * 256;
        const __half* kg = Kg + (size_t)(kt * FK) * (NKV * HD);
        const __half* vg = Vg + (size_t)(kt * FK) * (NKV * HD);
#pragma unroll
        for (int i = 0; i < 4; i++) {
            int id = tid + i * 256;
            int r = id >> 4, c = id & 15;
            uint32_t off = r * 256 + swz(c, r) * 16;
            cp_async16(ks + off, kg + (size_t)r * (NKV * HD) + c * 8);
            cp_async16(vs + off, vg + (size_t)r * (NKV * HD) + c * 8);
        }
        CP_COMMIT();
    };

    const int ntiles = 2 * qt + 2;
    load_kv(0, 0);

    float acc_o[16][4];
#pragma unroll
    for (int d = 0; d < 16; d++)
#pragma unroll
        for (int c = 0; c < 4; c++) acc_o[d][c] = 0.f;
    float mrow[2] = {-1e30f, -1e30f};
    float lrow[2] = {0.f, 0.f};

    const int row0 = qt * FQ + wid * 16 + g;

    for (int kt = 0; kt < ntiles; kt++) {
        if (kt + 1 < ntiles) { load_kv(kt + 1, (kt + 1) & 1); CP_WAIT(1); }
        else                 { CP_WAIT(0); }
        __syncthreads();

        const uint32_t ks = sb + QBYTES + (kt & 1) * KVSTAGE;
        const uint32_t vs = ks + FK * 256;

        float accs[8][4];
#pragma unroll
        for (int j = 0; j < 8; j++)
#pragma unroll
            for (int c = 0; c < 4; c++) accs[j][c] = 0.f;

#pragma unroll
        for (int d = 0; d < 8; d++) {
            uint32_t a[4];
            {
                int r = wid * 16 + lr;
                LDSM_X4(a, Qs + r * 256 + swz(d * 2 + lq, r) * 16);
            }
#pragma unroll
            for (int n = 0; n < 4; n++) {
                uint32_t kb[4];
                int r = n * 16 + lr;
                LDSM_X4(kb, ks + r * 256 + swz(d * 2 + lq, r) * 16);
                MMA16816(accs[n * 2],     a, kb[0], kb[2]);
                MMA16816(accs[n * 2 + 1], a, kb[1], kb[3]);
            }
        }

        const bool need_mask = (kt >= 2 * qt);
#pragma unroll
        for (int rr = 0; rr < 2; rr++) {
            const int grow = row0 + rr * 8;
            float mx = mrow[rr];
#pragma unroll
            for (int j = 0; j < 8; j++) {
                float s0 = accs[j][rr * 2] * scale;
                float s1 = accs[j][rr * 2 + 1] * scale;
                if (need_mask) {
                    int c0 = kt * FK + j * 8 + tq * 2;
                    if (c0 > grow)     s0 = -1e30f;
                    if (c0 + 1 > grow) s1 = -1e30f;
                }
                accs[j][rr * 2]     = s0;
                accs[j][rr * 2 + 1] = s1;
                mx = fmaxf(mx, fmaxf(s0, s1));
            }
            mx = fmaxf(mx, __shfl_xor_sync(0xFFFFFFFFu, mx, 1));
            mx = fmaxf(mx, __shfl_xor_sync(0xFFFFFFFFu, mx, 2));
            float corr = __expf(mrow[rr] - mx);
            mrow[rr] = mx;
            float ls = 0.f;
#pragma unroll
            for (int j = 0; j < 8; j++) {
                float p0 = __expf(accs[j][rr * 2] - mx);
                float p1 = __expf(accs[j][rr * 2 + 1] - mx);
                accs[j][rr * 2]     = p0;
                accs[j][rr * 2 + 1] = p1;
                ls += p0 + p1;
            }
            ls += __shfl_xor_sync(0xFFFFFFFFu, ls, 1);
            ls += __shfl_xor_sync(0xFFFFFFFFu, ls, 2);
            lrow[rr] = lrow[rr] * corr + ls;
#pragma unroll
            for (int d = 0; d < 16; d++) {
                acc_o[d][rr * 2]     *= corr;
                acc_o[d][rr * 2 + 1] *= corr;
            }
        }

        uint32_t p[8][2];
#pragma unroll
        for (int j = 0; j < 8; j++) {
            __half2 h0 = __floats2half2_rn(accs[j][0], accs[j][1]);
            __half2 h1 = __floats2half2_rn(accs[j][2], accs[j][3]);
            p[j][0] = *(uint32_t*)&h0;
            p[j][1] = *(uint32_t*)&h1;
        }

#pragma unroll
        for (int kk = 0; kk < 4; kk++) {
            uint32_t a[4] = {p[kk * 2][0], p[kk * 2][1],
                             p[kk * 2 + 1][0], p[kk * 2 + 1][1]};
#pragma unroll
            for (int dn = 0; dn < 8; dn++) {
                uint32_t vb[4];
                int r = kk * 16 + lr;
                LDSM_X4_T(vb, vs + r * 256 + swz(dn * 2 + lq, r) * 16);
                MMA16816(acc_o[dn * 2],     a, vb[0], vb[1]);
                MMA16816(acc_o[dn * 2 + 1], a, vb[2], vb[3]);
            }
        }
        __syncthreads();
    }

    const float il0 = 1.f / lrow[0];
    const float il1 = 1.f / lrow[1];
    __half* Og = Oh + ((size_t)(b * seq + row0) * NH + h) * HD;
#pragma unroll
    for (int dn = 0; dn < 16; dn++) {
        int d = dn * 8 + tq * 2;
        *(__half2*)(Og + d) =
            __floats2half2_rn(acc_o[dn][0] * il0, acc_o[dn][1] * il0);
        *(__half2*)(Og + (size_t)8 * (NH * HD) + d) =
            __floats2half2_rn(acc_o[dn][2] * il1, acc_o[dn][3] * il1);
    }
}

// ---------------- host side ------------------------------------------------
extern "C" void kernel_launch(void* const* d_in, const int* in_sizes, int n_in,
                              void* d_out, int out_size)
{
    const float* x  = (const float*)d_in[0];
    const float* wq = (const float*)d_in[1];
    const float* wk = (const float*)d_in[2];
    const float* wv = (const float*)d_in[3];
    const float* wo = (const float*)d_in[4];
    const float* fc = (const float*)d_in[7];
    const float* fs = (const float*)d_in[8];
    float* out = (float*)d_out;

    __half *xh, *wqkvh, *woh, *attnh, *qh, *kh, *vh;
    cudaGetSymbolAddress((void**)&xh,    g_xh);
    cudaGetSymbolAddress((void**)&wqkvh, g_wqkvh);
    cudaGetSymbolAddress((void**)&woh,   g_woh);
    cudaGetSymbolAddress((void**)&attnh, g_attnh);
    cudaGetSymbolAddress((void**)&qh,    g_qh);
    cudaGetSymbolAddress((void**)&kh,    g_kh);
    cudaGetSymbolAddress((void**)&vh,    g_vh);

    const int M = MTOT;

    // converts: x, wo plain; wq|wk|wv strided into concatenated [K][6144]
    f2h_kernel<<<(M * DIMM / 8 + 255) / 256, 256>>>(x,  xh,  M * DIMM / 8);
    f2h_kernel<<<(DIMM * DIMM / 8 + 255) / 256, 256>>>(wo, woh, DIMM * DIMM / 8);
    {
        int nq = DIMM * NH * HD / 8, nk = DIMM * NKV * HD / 8;
        f2h_strided<<<(nq + 255) / 256, 256>>>(wq, wqkvh, NH * HD / 8,  NQKV, 0,    nq);
        f2h_strided<<<(nk + 255) / 256, 256>>>(wk, wqkvh, NKV * HD / 8, NQKV, 4096, nk);
        f2h_strided<<<(nk + 255) / 256, 256>>>(wv, wqkvh, NKV * HD / 8, NQKV, 5120, nk);
    }

    cudaFuncSetAttribute(gemm_f16_256<0>, cudaFuncAttributeMaxDynamicSharedMemorySize,
                         GEMM_SMEM);
    cudaFuncSetAttribute(gemm_f16_256<1>, cudaFuncAttributeMaxDynamicSharedMemorySize,
                         GEMM_SMEM);

    // fused QKV projection + RoPE + fp16 epilogue
    gemm_f16_256<1><<<dim3(NQKV / GBN, M / GBM), 256, GEMM_SMEM>>>(
        xh, wqkvh, nullptr, qh, kh, vh, fc, fs, M, NQKV, DIMM);

    // fp16 tensor-core flash attention
    cudaFuncSetAttribute(flash_f16, cudaFuncAttributeMaxDynamicSharedMemorySize,
                         FA_SMEM);
    flash_f16<<<dim3(SEQL / FQ, NH, BSZ), 256, FA_SMEM>>>(qh, kh, vh, attnh, SEQL);

    // output projection (fp32 out)
    gemm_f16_256<0><<<dim3(DIMM / GBN, M / GBM), 256, GEMM_SMEM>>>(
        attnh, woh, out, nullptr, nullptr, nullptr, nullptr, nullptr, M, DIMM, DIMM);
}

// round 6
// speedup vs baseline: 8.5145x; 1.0177x over previous
#include <cuda_runtime.h>
#include <cuda_fp16.h>
#include <math.h>
#include <stdint.h>

#define BSZ  2
#define SEQL 2048
#define DIMM 4096
#define NH   32
#define NKV  8
#define HD   128
#define MTOT (BSZ * SEQL)          // 4096
#define NQKV (NH * HD + 2 * NKV * HD)   // 6144

// ---------------- scratch (__device__ globals) ----------------------------
__device__ __half g_xh[MTOT * DIMM];
__device__ __half g_wqkvh[DIMM * NQKV];
__device__ __half g_woh[DIMM * DIMM];
__device__ __half g_attnh[MTOT * NH * HD];
__device__ __half g_qh[MTOT * NH * HD];
__device__ __half g_kh[MTOT * NKV * HD];
__device__ __half g_vh[MTOT * NKV * HD];

// ---------------- PTX helpers ---------------------------------------------
__device__ __forceinline__ uint32_t smem_u32(const void* p) {
    uint32_t a;
    asm("{ .reg .u64 t; cvta.to.shared.u64 t, %1; cvt.u32.u64 %0, t; }"
        : "=r"(a) : "l"(p));
    return a;
}
__device__ __forceinline__ void cp_async16(uint32_t dst, const void* src) {
    asm volatile("cp.async.cg.shared.global [%0], [%1], 16;" :: "r"(dst), "l"(src));
}
#define CP_COMMIT() asm volatile("cp.async.commit_group;" ::: "memory")
#define CP_WAIT(n)  asm volatile("cp.async.wait_group %0;" :: "n"(n) : "memory")

#define LDSM_X4(R, addr) \
    asm volatile("ldmatrix.sync.aligned.m8n8.x4.shared.b16 {%0,%1,%2,%3}, [%4];" \
        : "=r"((R)[0]), "=r"((R)[1]), "=r"((R)[2]), "=r"((R)[3]) : "r"(addr))
#define LDSM_X4_T(R, addr) \
    asm volatile("ldmatrix.sync.aligned.m8n8.x4.trans.shared.b16 {%0,%1,%2,%3}, [%4];" \
        : "=r"((R)[0]), "=r"((R)[1]), "=r"((R)[2]), "=r"((R)[3]) : "r"(addr))

#define MMA16816(D, A, B0, B1) \
    asm volatile("mma.sync.aligned.m16n8k16.row.col.f32.f16.f16.f32 " \
        "{%0,%1,%2,%3}, {%4,%5,%6,%7}, {%8,%9}, {%0,%1,%2,%3};" \
        : "+f"((D)[0]), "+f"((D)[1]), "+f"((D)[2]), "+f"((D)[3]) \
        : "r"((A)[0]), "r"((A)[1]), "r"((A)[2]), "r"((A)[3]), "r"(B0), "r"(B1))

// ---------------- fp16 mma.sync GEMM, 128x256 tile, 16 warps ---------------
// MODE 0: C fp32 out. MODE 1: fused RoPE + fp16 split epilogue (q|k|v).
#define GBM 128
#define GBN 256
#define GBK 64
#define GST 4
#define A_STAGE 16384                      // 128 rows * 128 B
#define B_STAGE 32768                      // 64 rows * 4 blocks * 128 B
#define STAGE_BYTES (A_STAGE + B_STAGE)    // 49152
#define GEMM_SMEM (GST * STAGE_BYTES)      // 196608

template<int MODE>
__global__ __launch_bounds__(512, 1) void gemm_f16_256(
    const __half* __restrict__ A, const __half* __restrict__ B,
    float* __restrict__ C,
    __half* __restrict__ Qd, __half* __restrict__ Kd, __half* __restrict__ Vd,
    const float* __restrict__ cosb, const float* __restrict__ sinb,
    int M, int N, int K)
{
    extern __shared__ char smem[];
    const uint32_t sb = smem_u32(smem);
    const int tid  = threadIdx.x;
    const int lane = tid & 31;
    const int wid  = tid >> 5;
    const int mt   = blockIdx.y * GBM;
    const int nt   = blockIdx.x * GBN;
    const int wm   = (wid >> 2) * 32;      // 4x4 warp grid, 32x64 warp tile
    const int wn   = (wid & 3) * 64;
    const int NK   = K / GBK;

    float acc[2][8][4];
#pragma unroll
    for (int i = 0; i < 2; i++)
#pragma unroll
        for (int j = 0; j < 8; j++)
#pragma unroll
            for (int c = 0; c < 4; c++) acc[i][j][c] = 0.f;

    auto load_stage = [&](int kt, int s) {
        const uint32_t as = sb + s * STAGE_BYTES;
        const uint32_t bs = as + A_STAGE;
        const __half* Ag = A + (size_t)mt * K + kt * GBK;
        const __half* Bg = B + (size_t)(kt * GBK) * N + nt;
#pragma unroll
        for (int i = 0; i < 2; i++) {          // A: 1024 16B chunks
            int id = tid + i * 512;
            int r = id >> 3, c = id & 7;
            cp_async16(as + r * 128 + ((c ^ (r & 7)) << 4),
                       Ag + (size_t)r * K + c * 8);
        }
#pragma unroll
        for (int i = 0; i < 4; i++) {          // B: 2048 16B chunks
            int id = tid + i * 512;
            int r = id >> 5, c = id & 31;      // r 0..63, c 0..31
            uint32_t dst = bs + (c >> 3) * 8192 + r * 128 +
                           (((c & 7) ^ (r & 7)) << 4);
            cp_async16(dst, Bg + (size_t)r * N + c * 8);
        }
        CP_COMMIT();
    };

    for (int s = 0; s < GST - 1; s++) load_stage(s, s);

    const int lr = lane & 15;
    const int lq = lane >> 4;

    for (int kt = 0; kt < NK; kt++) {
        CP_WAIT(2);
        __syncthreads();
        if (kt + GST - 1 < NK) load_stage(kt + GST - 1, (kt + GST - 1) & (GST - 1));

        const uint32_t as = sb + (kt & (GST - 1)) * STAGE_BYTES;
        const uint32_t bs = as + A_STAGE;

#pragma unroll
        for (int ks = 0; ks < 4; ks++) {
            const int kk = ks * 16;
            uint32_t ar[2][4];
#pragma unroll
            for (int mf = 0; mf < 2; mf++) {
                int r = wm + mf * 16 + lr;
                LDSM_X4(ar[mf], as + r * 128 + ((((kk >> 3) + lq) ^ (r & 7)) << 4));
            }
            uint32_t br[4][4];
#pragma unroll
            for (int nf2 = 0; nf2 < 4; nf2++) {
                int n0 = wn + nf2 * 16;
                int r  = kk + lr;
                int cc = ((n0 & 63) >> 3) + lq;
                uint32_t addr = bs + (n0 >> 6) * 8192 + r * 128 +
                                ((cc ^ (r & 7)) << 4);
                LDSM_X4_T(br[nf2], addr);
            }
#pragma unroll
            for (int mf = 0; mf < 2; mf++)
#pragma unroll
                for (int nf = 0; nf < 8; nf++) {
                    uint32_t b0 = br[nf >> 1][(nf & 1) * 2];
                    uint32_t b1 = br[nf >> 1][(nf & 1) * 2 + 1];
                    MMA16816(acc[mf][nf], ar[mf], b0, b1);
                }
        }
    }

    const int g   = lane >> 2;
    const int tq  = lane & 3;

    if (MODE == 0) {
#pragma unroll
        for (int mf = 0; mf < 2; mf++) {
            int row0 = mt + wm + mf * 16 + g;
#pragma unroll
            for (int nf = 0; nf < 8; nf++) {
                int col = nt + wn + nf * 8 + tq * 2;
                *(float2*)(C + (size_t)row0 * N + col) =
                    make_float2(acc[mf][nf][0], acc[mf][nf][1]);
                *(float2*)(C + (size_t)(row0 + 8) * N + col) =
                    make_float2(acc[mf][nf][2], acc[mf][nf][3]);
            }
        }
    } else {
        // region: q cols [0,4096), k [4096,5120), v [5120,6144) — tile-aligned
        const int region = (nt >= 5 * 1024) ? 2 : (nt >= 4 * 1024 ? 1 : 0);
        __half* dst = region == 0 ? Qd : (region == 1 ? Kd : Vd);
        const int ld = region == 0 ? NH * HD : NKV * HD;
        const int cb = nt - (region == 0 ? 0 : (region == 1 ? 4096 : 5120));
        const bool dorope = (region < 2);
#pragma unroll
        for (int mf = 0; mf < 2; mf++) {
            int r0 = mt + wm + mf * 16 + g;
            int s0 = r0 & (SEQL - 1);
            int s1 = (r0 + 8) & (SEQL - 1);
#pragma unroll
            for (int nf = 0; nf < 8; nf++) {
                int colg = wn + nf * 8 + tq * 2;
                float a0 = acc[mf][nf][0], a1 = acc[mf][nf][1];
                float a2 = acc[mf][nf][2], a3 = acc[mf][nf][3];
                __half2 h0, h1;
                if (dorope) {
                    int i = ((nt + colg) & 127) >> 1;
                    float c0 = cosb[s0 * 64 + i], n0 = sinb[s0 * 64 + i];
                    float c1 = cosb[s1 * 64 + i], n1 = sinb[s1 * 64 + i];
                    h0 = __floats2half2_rn(a0 * c0 - a1 * n0, a0 * n0 + a1 * c0);
                    h1 = __floats2half2_rn(a2 * c1 - a3 * n1, a2 * n1 + a3 * c1);
                } else {
                    h0 = __floats2half2_rn(a0, a1);
                    h1 = __floats2half2_rn(a2, a3);
                }
                *(__half2*)(dst + (size_t)r0 * ld + cb + colg) = h0;
                *(__half2*)(dst + (size_t)(r0 + 8) * ld + cb + colg) = h1;
            }
        }
    }
}

// ---------------- one fused fp32 -> fp16 convert kernel --------------------
// segments (uint4 granularity): x | wo | wq(strided) | wk(strided) | wv(strided)
#define CNX  (MTOT * DIMM / 8)
#define CNWO (DIMM * DIMM / 8)
#define CNWQ (DIMM * NH * HD / 8)
#define CNWK (DIMM * NKV * HD / 8)
#define CTOT (CNX + CNWO + CNWQ + 2 * CNWK)

__device__ __forceinline__ uint4 cvt8(const float* p) {
    float4 v0 = ((const float4*)p)[0];
    float4 v1 = ((const float4*)p)[1];
    union { uint4 u; __half2 h[4]; } r;
    r.h[0] = __floats2half2_rn(v0.x, v0.y);
    r.h[1] = __floats2half2_rn(v0.z, v0.w);
    r.h[2] = __floats2half2_rn(v1.x, v1.y);
    r.h[3] = __floats2half2_rn(v1.z, v1.w);
    return r.u;
}

__global__ void convert_all(const float* __restrict__ x,
                            const float* __restrict__ wq,
                            const float* __restrict__ wk,
                            const float* __restrict__ wv,
                            const float* __restrict__ wo,
                            __half* __restrict__ xh,
                            __half* __restrict__ wqkvh,
                            __half* __restrict__ woh)
{
    int i = blockIdx.x * blockDim.x + threadIdx.x;
    if (i >= CTOT) return;
    if (i < CNX) {
        ((uint4*)xh)[i] = cvt8(x + (size_t)i * 8);
    } else if (i < CNX + CNWO) {
        int j = i - CNX;
        ((uint4*)woh)[j] = cvt8(wo + (size_t)j * 8);
    } else if (i < CNX + CNWO + CNWQ) {
        int j = i - CNX - CNWO;
        int r = j >> 9, c = j & 511;           // 512 chunks per 4096-col row
        *(uint4*)(wqkvh + (size_t)r * NQKV + c * 8) = cvt8(wq + (size_t)j * 8);
    } else if (i < CNX + CNWO + CNWQ + CNWK) {
        int j = i - CNX - CNWO - CNWQ;
        int r = j >> 7, c = j & 127;           // 128 chunks per 1024-col row
        *(uint4*)(wqkvh + (size_t)r * NQKV + 4096 + c * 8) = cvt8(wk + (size_t)j * 8);
    } else {
        int j = i - CNX - CNWO - CNWQ - CNWK;
        int r = j >> 7, c = j & 127;
        *(uint4*)(wqkvh + (size_t)r * NQKV + 5120 + c * 8) = cvt8(wv + (size_t)j * 8);
    }
}

// ---------------- fp16 tensor-core flash attention -------------------------
#define FQ 128
#define FK 64
#define QBYTES   (FQ * 256)
#define KVSTAGE  (FK * 256 * 2)
#define FA_SMEM  (QBYTES + 2 * KVSTAGE)

__device__ __forceinline__ uint32_t swz(uint32_t c, uint32_t r) {
    return ((c ^ (r & 7)) & 7) | (c & 8);
}

__global__ __launch_bounds__(256, 1) void flash_f16(
    const __half* __restrict__ Qh, const __half* __restrict__ Kh,
    const __half* __restrict__ Vh, __half* __restrict__ Oh, int seq)
{
    extern __shared__ char smc[];
    const uint32_t sb = smem_u32(smc);
    const uint32_t Qs = sb;

    const int qt = blockIdx.x, h = blockIdx.y, b = blockIdx.z;
    const int kvh = h >> 2;
    const int tid = threadIdx.x, lane = tid & 31, wid = tid >> 5;
    const int lr = lane & 15, lq = lane >> 4;
    const int g = lane >> 2, tq = lane & 3;
    const float scale = 0.08838834764831845f;

    const __half* Qg = Qh + ((size_t)(b * seq + qt * FQ) * NH + h) * HD;
    const __half* Kg = Kh + ((size_t)b * seq * NKV + kvh) * HD;
    const __half* Vg = Vh + ((size_t)b * seq * NKV + kvh) * HD;

#pragma unroll
    for (int i = 0; i < 8; i++) {
        int id = tid + i * 256;
        int r = id >> 4, c = id & 15;
        cp_async16(Qs + r * 256 + swz(c, r) * 16, Qg + (size_t)r * (NH * HD) + c * 8);
    }
    CP_COMMIT();

    auto load_kv = [&](int kt, int s) {
        uint32_t ks = sb + QBYTES + s * KVSTAGE;
        uint32_t vs = ks + FK * 256;
        const __half* kg = Kg + (size_t)(kt * FK) * (NKV * HD);
        const __half* vg = Vg + (size_t)(kt * FK) * (NKV * HD);
#pragma unroll
        for (int i = 0; i < 4; i++) {
            int id = tid + i * 256;
            int r = id >> 4, c = id & 15;
            uint32_t off = r * 256 + swz(c, r) * 16;
            cp_async16(ks + off, kg + (size_t)r * (NKV * HD) + c * 8);
            cp_async16(vs + off, vg + (size_t)r * (NKV * HD) + c * 8);
        }
        CP_COMMIT();
    };

    const int ntiles = 2 * qt + 2;
    load_kv(0, 0);

    float acc_o[16][4];
#pragma unroll
    for (int d = 0; d < 16; d++)
#pragma unroll
        for (int c = 0; c < 4; c++) acc_o[d][c] = 0.f;
    float mrow[2] = {-1e30f, -1e30f};
    float lrow[2] = {0.f, 0.f};

    const int row0 = qt * FQ + wid * 16 + g;

    for (int kt = 0; kt < ntiles; kt++) {
        if (kt + 1 < ntiles) { load_kv(kt + 1, (kt + 1) & 1); CP_WAIT(1); }
        else                 { CP_WAIT(0); }
        __syncthreads();

        const uint32_t ks = sb + QBYTES + (kt & 1) * KVSTAGE;
        const uint32_t vs = ks + FK * 256;

        float accs[8][4];
#pragma unroll
        for (int j = 0; j < 8; j++)
#pragma unroll
            for (int c = 0; c < 4; c++) accs[j][c] = 0.f;

#pragma unroll
        for (int d = 0; d < 8; d++) {
            uint32_t a[4];
            {
                int r = wid * 16 + lr;
                LDSM_X4(a, Qs + r * 256 + swz(d * 2 + lq, r) * 16);
            }
#pragma unroll
            for (int n = 0; n < 4; n++) {
                uint32_t kb[4];
                int r = n * 16 + lr;
                LDSM_X4(kb, ks + r * 256 + swz(d * 2 + lq, r) * 16);
                MMA16816(accs[n * 2],     a, kb[0], kb[2]);
                MMA16816(accs[n * 2 + 1], a, kb[1], kb[3]);
            }
        }

        const bool need_mask = (kt >= 2 * qt);
#pragma unroll
        for (int rr = 0; rr < 2; rr++) {
            const int grow = row0 + rr * 8;
            float mx = mrow[rr];
#pragma unroll
            for (int j = 0; j < 8; j++) {
                float s0 = accs[j][rr * 2] * scale;
                float s1 = accs[j][rr * 2 + 1] * scale;
                if (need_mask) {
                    int c0 = kt * FK + j * 8 + tq * 2;
                    if (c0 > grow)     s0 = -1e30f;
                    if (c0 + 1 > grow) s1 = -1e30f;
                }
                accs[j][rr * 2]     = s0;
                accs[j][rr * 2 + 1] = s1;
                mx = fmaxf(mx, fmaxf(s0, s1));
            }
            mx = fmaxf(mx, __shfl_xor_sync(0xFFFFFFFFu, mx, 1));
            mx = fmaxf(mx, __shfl_xor_sync(0xFFFFFFFFu, mx, 2));
            float corr = __expf(mrow[rr] - mx);
            mrow[rr] = mx;
            float ls = 0.f;
#pragma unroll
            for (int j = 0; j < 8; j++) {
                float p0 = __expf(accs[j][rr * 2] - mx);
                float p1 = __expf(accs[j][rr * 2 + 1] - mx);
                accs[j][rr * 2]     = p0;
                accs[j][rr * 2 + 1] = p1;
                ls += p0 + p1;
            }
            ls += __shfl_xor_sync(0xFFFFFFFFu, ls, 1);
            ls += __shfl_xor_sync(0xFFFFFFFFu, ls, 2);
            lrow[rr] = lrow[rr] * corr + ls;
#pragma unroll
            for (int d = 0; d < 16; d++) {
                acc_o[d][rr * 2]     *= corr;
                acc_o[d][rr * 2 + 1] *= corr;
            }
        }

        uint32_t p[8][2];
#pragma unroll
        for (int j = 0; j < 8; j++) {
            __half2 h0 = __floats2half2_rn(accs[j][0], accs[j][1]);
            __half2 h1 = __floats2half2_rn(accs[j][2], accs[j][3]);
            p[j][0] = *(uint32_t*)&h0;
            p[j][1] = *(uint32_t*)&h1;
        }

#pragma unroll
        for (int kk = 0; kk < 4; kk++) {
            uint32_t a[4] = {p[kk * 2][0], p[kk * 2][1],
                             p[kk * 2 + 1][0], p[kk * 2 + 1][1]};
#pragma unroll
            for (int dn = 0; dn < 8; dn++) {
                uint32_t vb[4];
                int r = kk * 16 + lr;
                LDSM_X4_T(vb, vs + r * 256 + swz(dn * 2 + lq, r) * 16);
                MMA16816(acc_o[dn * 2],     a, vb[0], vb[1]);
                MMA16816(acc_o[dn * 2 + 1], a, vb[2], vb[3]);
            }
        }
        __syncthreads();
    }

    const float il0 = 1.f / lrow[0];
    const float il1 = 1.f / lrow[1];
    __half* Og = Oh + ((size_t)(b * seq + row0) * NH + h) * HD;
#pragma unroll
    for (int dn = 0; dn < 16; dn++) {
        int d = dn * 8 + tq * 2;
        *(__half2*)(Og + d) =
            __floats2half2_rn(acc_o[dn][0] * il0, acc_o[dn][1] * il0);
        *(__half2*)(Og + (size_t)8 * (NH * HD) + d) =
            __floats2half2_rn(acc_o[dn][2] * il1, acc_o[dn][3] * il1);
    }
}

// ---------------- host side ------------------------------------------------
extern "C" void kernel_launch(void* const* d_in, const int* in_sizes, int n_in,
                              void* d_out, int out_size)
{
    const float* x  = (const float*)d_in[0];
    const float* wq = (const float*)d_in[1];
    const float* wk = (const float*)d_in[2];
    const float* wv = (const float*)d_in[3];
    const float* wo = (const float*)d_in[4];
    const float* fc = (const float*)d_in[7];
    const float* fs = (const float*)d_in[8];
    float* out = (float*)d_out;

    __half *xh, *wqkvh, *woh, *attnh, *qh, *kh, *vh;
    cudaGetSymbolAddress((void**)&xh,    g_xh);
    cudaGetSymbolAddress((void**)&wqkvh, g_wqkvh);
    cudaGetSymbolAddress((void**)&woh,   g_woh);
    cudaGetSymbolAddress((void**)&attnh, g_attnh);
    cudaGetSymbolAddress((void**)&qh,    g_qh);
    cudaGetSymbolAddress((void**)&kh,    g_kh);
    cudaGetSymbolAddress((void**)&vh,    g_vh);

    const int M = MTOT;

    // single fused convert pass
    convert_all<<<(CTOT + 255) / 256, 256>>>(x, wq, wk, wv, wo, xh, wqkvh, woh);

    cudaFuncSetAttribute(gemm_f16_256<0>, cudaFuncAttributeMaxDynamicSharedMemorySize,
                         GEMM_SMEM);
    cudaFuncSetAttribute(gemm_f16_256<1>, cudaFuncAttributeMaxDynamicSharedMemorySize,
                         GEMM_SMEM);

    // fused QKV projection + RoPE + fp16 epilogue
    gemm_f16_256<1><<<dim3(NQKV / GBN, M / GBM), 512, GEMM_SMEM>>>(
        xh, wqkvh, nullptr, qh, kh, vh, fc, fs, M, NQKV, DIMM);

    // fp16 tensor-core flash attention
    cudaFuncSetAttribute(flash_f16, cudaFuncAttributeMaxDynamicSharedMemorySize,
                         FA_SMEM);
    flash_f16<<<dim3(SEQL / FQ, NH, BSZ), 256, FA_SMEM>>>(qh, kh, vh, attnh, SEQL);

    // output projection (fp32 out)
    gemm_f16_256<0><<<dim3(DIMM / GBN, M / GBM), 512, GEMM_SMEM>>>(
        attnh, woh, out, nullptr, nullptr, nullptr, nullptr, nullptr, M, DIMM, DIMM);
}

// round 7
// speedup vs baseline: 8.7756x; 1.0307x over previous
#include <cuda_runtime.h>
#include <cuda_fp16.h>
#include <math.h>
#include <stdint.h>

#define BSZ  2
#define SEQL 2048
#define DIMM 4096
#define NH   32
#define NKV  8
#define HD   128
#define MTOT (BSZ * SEQL)          // 4096
#define NQKV (NH * HD + 2 * NKV * HD)   // 6144

// ---------------- scratch (__device__ globals) ----------------------------
__device__ __half g_xh[MTOT * DIMM];
__device__ __half g_wqkvh[DIMM * NQKV];
__device__ __half g_woh[DIMM * DIMM];
__device__ __half g_attnh[MTOT * NH * HD];
__device__ __half g_qh[MTOT * NH * HD];
__device__ __half g_kh[MTOT * NKV * HD];
__device__ __half g_vh[MTOT * NKV * HD];

// ---------------- PTX helpers ---------------------------------------------
__device__ __forceinline__ uint32_t smem_u32(const void* p) {
    uint32_t a;
    asm("{ .reg .u64 t; cvta.to.shared.u64 t, %1; cvt.u32.u64 %0, t; }"
        : "=r"(a) : "l"(p));
    return a;
}
__device__ __forceinline__ void cp_async16(uint32_t dst, const void* src) {
    asm volatile("cp.async.cg.shared.global [%0], [%1], 16;" :: "r"(dst), "l"(src));
}
#define CP_COMMIT() asm volatile("cp.async.commit_group;" ::: "memory")
#define CP_WAIT(n)  asm volatile("cp.async.wait_group %0;" :: "n"(n) : "memory")

#define LDSM_X4(R, addr) \
    asm volatile("ldmatrix.sync.aligned.m8n8.x4.shared.b16 {%0,%1,%2,%3}, [%4];" \
        : "=r"((R)[0]), "=r"((R)[1]), "=r"((R)[2]), "=r"((R)[3]) : "r"(addr))
#define LDSM_X4_T(R, addr) \
    asm volatile("ldmatrix.sync.aligned.m8n8.x4.trans.shared.b16 {%0,%1,%2,%3}, [%4];" \
        : "=r"((R)[0]), "=r"((R)[1]), "=r"((R)[2]), "=r"((R)[3]) : "r"(addr))

#define MMA16816(D, A, B0, B1) \
    asm volatile("mma.sync.aligned.m16n8k16.row.col.f32.f16.f16.f32 " \
        "{%0,%1,%2,%3}, {%4,%5,%6,%7}, {%8,%9}, {%0,%1,%2,%3};" \
        : "+f"((D)[0]), "+f"((D)[1]), "+f"((D)[2]), "+f"((D)[3]) \
        : "r"((A)[0]), "r"((A)[1]), "r"((A)[2]), "r"((A)[3]), "r"(B0), "r"(B1))

// ---------------- fp16 mma.sync GEMM, 128x256, 8 warps, frag-pipelined ----
// MODE 0: C fp32 out. MODE 1: fused RoPE + fp16 split epilogue (q|k|v).
#define GBM 128
#define GBN 256
#define GBK 64
#define GST 4
#define A_STAGE 16384                      // 128 rows * 128 B
#define B_STAGE 32768                      // 64 rows * 4 blocks * 128 B
#define STAGE_BYTES (A_STAGE + B_STAGE)    // 49152
#define GEMM_SMEM (GST * STAGE_BYTES)      // 196608

template<int MODE>
__global__ __launch_bounds__(256, 1) void gemm_f16_256(
    const __half* __restrict__ A, const __half* __restrict__ B,
    float* __restrict__ C,
    __half* __restrict__ Qd, __half* __restrict__ Kd, __half* __restrict__ Vd,
    const float* __restrict__ cosb, const float* __restrict__ sinb,
    int M, int N, int K)
{
    extern __shared__ char smem[];
    const uint32_t sb = smem_u32(smem);
    const int tid  = threadIdx.x;
    const int lane = tid & 31;
    const int wid  = tid >> 5;
    const int mt   = blockIdx.y * GBM;
    const int nt   = blockIdx.x * GBN;
    const int wm   = (wid >> 2) * 64;      // 2x4 warp grid, 64x64 warp tile
    const int wn   = (wid & 3) * 64;
    const int NK   = K / GBK;

    float acc[4][8][4];
#pragma unroll
    for (int i = 0; i < 4; i++)
#pragma unroll
        for (int j = 0; j < 8; j++)
#pragma unroll
            for (int c = 0; c < 4; c++) acc[i][j][c] = 0.f;

    auto load_stage = [&](int kt, int s) {
        const uint32_t as = sb + s * STAGE_BYTES;
        const uint32_t bs = as + A_STAGE;
        const __half* Ag = A + (size_t)mt * K + kt * GBK;
        const __half* Bg = B + (size_t)(kt * GBK) * N + nt;
#pragma unroll
        for (int i = 0; i < 4; i++) {          // A: 1024 16B chunks
            int id = tid + i * 256;
            int r = id >> 3, c = id & 7;
            cp_async16(as + r * 128 + ((c ^ (r & 7)) << 4),
                       Ag + (size_t)r * K + c * 8);
        }
#pragma unroll
        for (int i = 0; i < 8; i++) {          // B: 2048 16B chunks
            int id = tid + i * 256;
            int r = id >> 5, c = id & 31;      // r 0..63, c 0..31
            uint32_t dst = bs + (c >> 3) * 8192 + r * 128 +
                           (((c & 7) ^ (r & 7)) << 4);
            cp_async16(dst, Bg + (size_t)r * N + c * 8);
        }
        CP_COMMIT();
    };

    for (int s = 0; s < GST - 1; s++) load_stage(s, s);

    const int lr = lane & 15;
    const int lq = lane >> 4;

    // double-buffered fragments
    uint32_t ar[2][4][4], br[2][4][4];

    auto load_frags = [&](int ks, int buf, uint32_t as, uint32_t bs) {
        const int kk = ks * 16;
#pragma unroll
        for (int mf = 0; mf < 4; mf++) {
            int r = wm + mf * 16 + lr;
            LDSM_X4(ar[buf][mf], as + r * 128 + ((((kk >> 3) + lq) ^ (r & 7)) << 4));
        }
#pragma unroll
        for (int nf2 = 0; nf2 < 4; nf2++) {
            int n0 = wn + nf2 * 16;
            int r  = kk + lr;
            int cc = ((n0 & 63) >> 3) + lq;
            LDSM_X4_T(br[buf][nf2], bs + (n0 >> 6) * 8192 + r * 128 +
                                    ((cc ^ (r & 7)) << 4));
        }
    };

    for (int kt = 0; kt < NK; kt++) {
        CP_WAIT(2);
        __syncthreads();

        const uint32_t as = sb + (kt & (GST - 1)) * STAGE_BYTES;
        const uint32_t bs = as + A_STAGE;

        load_frags(0, 0, as, bs);              // prefetch first k-slice
        if (kt + GST - 1 < NK) load_stage(kt + GST - 1, (kt + GST - 1) & (GST - 1));

#pragma unroll
        for (int ks = 0; ks < 4; ks++) {
            const int cur = ks & 1;
            if (ks < 3) load_frags(ks + 1, cur ^ 1, as, bs);
#pragma unroll
            for (int mf = 0; mf < 4; mf++)
#pragma unroll
                for (int nf = 0; nf < 8; nf++) {
                    uint32_t b0 = br[cur][nf >> 1][(nf & 1) * 2];
                    uint32_t b1 = br[cur][nf >> 1][(nf & 1) * 2 + 1];
                    MMA16816(acc[mf][nf], ar[cur][mf], b0, b1);
                }
        }
    }

    const int g   = lane >> 2;
    const int tq  = lane & 3;

    if (MODE == 0) {
#pragma unroll
        for (int mf = 0; mf < 4; mf++) {
            int row0 = mt + wm + mf * 16 + g;
#pragma unroll
            for (int nf = 0; nf < 8; nf++) {
                int col = nt + wn + nf * 8 + tq * 2;
                *(float2*)(C + (size_t)row0 * N + col) =
                    make_float2(acc[mf][nf][0], acc[mf][nf][1]);
                *(float2*)(C + (size_t)(row0 + 8) * N + col) =
                    make_float2(acc[mf][nf][2], acc[mf][nf][3]);
            }
        }
    } else {
        // region: q cols [0,4096), k [4096,5120), v [5120,6144) — tile-aligned
        const int region = (nt >= 5 * 1024) ? 2 : (nt >= 4 * 1024 ? 1 : 0);
        __half* dst = region == 0 ? Qd : (region == 1 ? Kd : Vd);
        const int ld = region == 0 ? NH * HD : NKV * HD;
        const int cb = nt - (region == 0 ? 0 : (region == 1 ? 4096 : 5120));
        const bool dorope = (region < 2);
#pragma unroll
        for (int mf = 0; mf < 4; mf++) {
            int r0 = mt + wm + mf * 16 + g;
            int s0 = r0 & (SEQL - 1);
            int s1 = (r0 + 8) & (SEQL - 1);
#pragma unroll
            for (int nf = 0; nf < 8; nf++) {
                int colg = wn + nf * 8 + tq * 2;
                float a0 = acc[mf][nf][0], a1 = acc[mf][nf][1];
                float a2 = acc[mf][nf][2], a3 = acc[mf][nf][3];
                __half2 h0, h1;
                if (dorope) {
                    int i = ((nt + colg) & 127) >> 1;
                    float c0 = cosb[s0 * 64 + i], n0 = sinb[s0 * 64 + i];
                    float c1 = cosb[s1 * 64 + i], n1 = sinb[s1 * 64 + i];
                    h0 = __floats2half2_rn(a0 * c0 - a1 * n0, a0 * n0 + a1 * c0);
                    h1 = __floats2half2_rn(a2 * c1 - a3 * n1, a2 * n1 + a3 * c1);
                } else {
                    h0 = __floats2half2_rn(a0, a1);
                    h1 = __floats2half2_rn(a2, a3);
                }
                *(__half2*)(dst + (size_t)r0 * ld + cb + colg) = h0;
                *(__half2*)(dst + (size_t)(r0 + 8) * ld + cb + colg) = h1;
            }
        }
    }
}

// ---------------- one fused fp32 -> fp16 convert kernel --------------------
#define CNX  (MTOT * DIMM / 8)
#define CNWO (DIMM * DIMM / 8)
#define CNWQ (DIMM * NH * HD / 8)
#define CNWK (DIMM * NKV * HD / 8)
#define CTOT (CNX + CNWO + CNWQ + 2 * CNWK)

__device__ __forceinline__ uint4 cvt8(const float* p) {
    float4 v0 = ((const float4*)p)[0];
    float4 v1 = ((const float4*)p)[1];
    union { uint4 u; __half2 h[4]; } r;
    r.h[0] = __floats2half2_rn(v0.x, v0.y);
    r.h[1] = __floats2half2_rn(v0.z, v0.w);
    r.h[2] = __floats2half2_rn(v1.x, v1.y);
    r.h[3] = __floats2half2_rn(v1.z, v1.w);
    return r.u;
}

__global__ void convert_all(const float* __restrict__ x,
                            const float* __restrict__ wq,
                            const float* __restrict__ wk,
                            const float* __restrict__ wv,
                            const float* __restrict__ wo,
                            __half* __restrict__ xh,
                            __half* __restrict__ wqkvh,
                            __half* __restrict__ woh)
{
    int i = blockIdx.x * blockDim.x + threadIdx.x;
    if (i >= CTOT) return;
    if (i < CNX) {
        ((uint4*)xh)[i] = cvt8(x + (size_t)i * 8);
    } else if (i < CNX + CNWO) {
        int j = i - CNX;
        ((uint4*)woh)[j] = cvt8(wo + (size_t)j * 8);
    } else if (i < CNX + CNWO + CNWQ) {
        int j = i - CNX - CNWO;
        int r = j >> 9, c = j & 511;
        *(uint4*)(wqkvh + (size_t)r * NQKV + c * 8) = cvt8(wq + (size_t)j * 8);
    } else if (i < CNX + CNWO + CNWQ + CNWK) {
        int j = i - CNX - CNWO - CNWQ;
        int r = j >> 7, c = j & 127;
        *(uint4*)(wqkvh + (size_t)r * NQKV + 4096 + c * 8) = cvt8(wk + (size_t)j * 8);
    } else {
        int j = i - CNX - CNWO - CNWQ - CNWK;
        int r = j >> 7, c = j & 127;
        *(uint4*)(wqkvh + (size_t)r * NQKV + 5120 + c * 8) = cvt8(wv + (size_t)j * 8);
    }
}

// ---------------- fp16 tensor-core flash attention -------------------------
#define FQ 128
#define FK 64
#define QBYTES   (FQ * 256)
#define KVSTAGE  (FK * 256 * 2)
#define FA_SMEM  (QBYTES + 2 * KVSTAGE)

__device__ __forceinline__ uint32_t swz(uint32_t c, uint32_t r) {
    return ((c ^ (r & 7)) & 7) | (c & 8);
}

__global__ __launch_bounds__(256, 1) void flash_f16(
    const __half* __restrict__ Qh, const __half* __restrict__ Kh,
    const __half* __restrict__ Vh, __half* __restrict__ Oh, int seq)
{
    extern __shared__ char smc[];
    const uint32_t sb = smem_u32(smc);
    const uint32_t Qs = sb;

    const int qt = blockIdx.x, h = blockIdx.y, b = blockIdx.z;
    const int kvh = h >> 2;
    const int tid = threadIdx.x, lane = tid & 31, wid = tid >> 5;
    const int lr = lane & 15, lq = lane >> 4;
    const int g = lane >> 2, tq = lane & 3;
    const float scale = 0.08838834764831845f;

    const __half* Qg = Qh + ((size_t)(b * seq + qt * FQ) * NH + h) * HD;
    const __half* Kg = Kh + ((size_t)b * seq * NKV + kvh) * HD;
    const __half* Vg = Vh + ((size_t)b * seq * NKV + kvh) * HD;

#pragma unroll
    for (int i = 0; i < 8; i++) {
        int id = tid + i * 256;
        int r = id >> 4, c = id & 15;
        cp_async16(Qs + r * 256 + swz(c, r) * 16, Qg + (size_t)r * (NH * HD) + c * 8);
    }
    CP_COMMIT();

    auto load_kv = [&](int kt, int s) {
        uint32_t ks = sb + QBYTES + s * KVSTAGE;
        uint32_t vs = ks + FK * 256;
        const __half* kg = Kg + (size_t)(kt * FK) * (NKV * HD);
        const __half* vg = Vg + (size_t)(kt * FK) * (NKV * HD);
#pragma unroll
        for (int i = 0; i < 4; i++) {
            int id = tid + i * 256;
            int r = id >> 4, c = id & 15;
            uint32_t off = r * 256 + swz(c, r) * 16;
            cp_async16(ks + off, kg + (size_t)r * (NKV * HD) + c * 8);
            cp_async16(vs + off, vg + (size_t)r * (NKV * HD) + c * 8);
        }
        CP_COMMIT();
    };

    const int ntiles = 2 * qt + 2;
    load_kv(0, 0);

    float acc_o[16][4];
#pragma unroll
    for (int d = 0; d < 16; d++)
#pragma unroll
        for (int c = 0; c < 4; c++) acc_o[d][c] = 0.f;
    float mrow[2] = {-1e30f, -1e30f};
    float lrow[2] = {0.f, 0.f};

    const int row0 = qt * FQ + wid * 16 + g;

    for (int kt = 0; kt < ntiles; kt++) {
        if (kt + 1 < ntiles) { load_kv(kt + 1, (kt + 1) & 1); CP_WAIT(1); }
        else                 { CP_WAIT(0); }
        __syncthreads();

        const uint32_t ks = sb + QBYTES + (kt & 1) * KVSTAGE;
        const uint32_t vs = ks + FK * 256;

        float accs[8][4];
#pragma unroll
        for (int j = 0; j < 8; j++)
#pragma unroll
            for (int c = 0; c < 4; c++) accs[j][c] = 0.f;

#pragma unroll
        for (int d = 0; d < 8; d++) {
            uint32_t a[4];
            {
                int r = wid * 16 + lr;
                LDSM_X4(a, Qs + r * 256 + swz(d * 2 + lq, r) * 16);
            }
#pragma unroll
            for (int n = 0; n < 4; n++) {
                uint32_t kb[4];
                int r = n * 16 + lr;
                LDSM_X4(kb, ks + r * 256 + swz(d * 2 + lq, r) * 16);
                MMA16816(accs[n * 2],     a, kb[0], kb[2]);
                MMA16816(accs[n * 2 + 1], a, kb[1], kb[3]);
            }
        }

        const bool need_mask = (kt >= 2 * qt);
#pragma unroll
        for (int rr = 0; rr < 2; rr++) {
            const int grow = row0 + rr * 8;
            float mx = mrow[rr];
#pragma unroll
            for (int j = 0; j < 8; j++) {
                float s0 = accs[j][rr * 2] * scale;
                float s1 = accs[j][rr * 2 + 1] * scale;
                if (need_mask) {
                    int c0 = kt * FK + j * 8 + tq * 2;
                    if (c0 > grow)     s0 = -1e30f;
                    if (c0 + 1 > grow) s1 = -1e30f;
                }
                accs[j][rr * 2]     = s0;
                accs[j][rr * 2 + 1] = s1;
                mx = fmaxf(mx, fmaxf(s0, s1));
            }
            mx = fmaxf(mx, __shfl_xor_sync(0xFFFFFFFFu, mx, 1));
            mx = fmaxf(mx, __shfl_xor_sync(0xFFFFFFFFu, mx, 2));
            float corr = __expf(mrow[rr] - mx);
            mrow[rr] = mx;
            float ls = 0.f;
#pragma unroll
            for (int j = 0; j < 8; j++) {
                float p0 = __expf(accs[j][rr * 2] - mx);
                float p1 = __expf(accs[j][rr * 2 + 1] - mx);
                accs[j][rr * 2]     = p0;
                accs[j][rr * 2 + 1] = p1;
                ls += p0 + p1;
            }
            ls += __shfl_xor_sync(0xFFFFFFFFu, ls, 1);
            ls += __shfl_xor_sync(0xFFFFFFFFu, ls, 2);
            lrow[rr] = lrow[rr] * corr + ls;
#pragma unroll
            for (int d = 0; d < 16; d++) {
                acc_o[d][rr * 2]     *= corr;
                acc_o[d][rr * 2 + 1] *= corr;
            }
        }

        uint32_t p[8][2];
#pragma unroll
        for (int j = 0; j < 8; j++) {
            __half2 h0 = __floats2half2_rn(accs[j][0], accs[j][1]);
            __half2 h1 = __floats2half2_rn(accs[j][2], accs[j][3]);
            p[j][0] = *(uint32_t*)&h0;
            p[j][1] = *(uint32_t*)&h1;
        }

#pragma unroll
        for (int kk = 0; kk < 4; kk++) {
            uint32_t a[4] = {p[kk * 2][0], p[kk * 2][1],
                             p[kk * 2 + 1][0], p[kk * 2 + 1][1]};
#pragma unroll
            for (int dn = 0; dn < 8; dn++) {
                uint32_t vb[4];
                int r = kk * 16 + lr;
                LDSM_X4_T(vb, vs + r * 256 + swz(dn * 2 + lq, r) * 16);
                MMA16816(acc_o[dn * 2],     a, vb[0], vb[1]);
                MMA16816(acc_o[dn * 2 + 1], a, vb[2], vb[3]);
            }
        }
        __syncthreads();
    }

    const float il0 = 1.f / lrow[0];
    const float il1 = 1.f / lrow[1];
    __half* Og = Oh + ((size_t)(b * seq + row0) * NH + h) * HD;
#pragma unroll
    for (int dn = 0; dn < 16; dn++) {
        int d = dn * 8 + tq * 2;
        *(__half2*)(Og + d) =
            __floats2half2_rn(acc_o[dn][0] * il0, acc_o[dn][1] * il0);
        *(__half2*)(Og + (size_t)8 * (NH * HD) + d) =
            __floats2half2_rn(acc_o[dn][2] * il1, acc_o[dn][3] * il1);
    }
}

// ---------------- host side ------------------------------------------------
extern "C" void kernel_launch(void* const* d_in, const int* in_sizes, int n_in,
                              void* d_out, int out_size)
{
    const float* x  = (const float*)d_in[0];
    const float* wq = (const float*)d_in[1];
    const float* wk = (const float*)d_in[2];
    const float* wv = (const float*)d_in[3];
    const float* wo = (const float*)d_in[4];
    const float* fc = (const float*)d_in[7];
    const float* fs = (const float*)d_in[8];
    float* out = (float*)d_out;

    __half *xh, *wqkvh, *woh, *attnh, *qh, *kh, *vh;
    cudaGetSymbolAddress((void**)&xh,    g_xh);
    cudaGetSymbolAddress((void**)&wqkvh, g_wqkvh);
    cudaGetSymbolAddress((void**)&woh,   g_woh);
    cudaGetSymbolAddress((void**)&attnh, g_attnh);
    cudaGetSymbolAddress((void**)&qh,    g_qh);
    cudaGetSymbolAddress((void**)&kh,    g_kh);
    cudaGetSymbolAddress((void**)&vh,    g_vh);

    const int M = MTOT;

    convert_all<<<(CTOT + 255) / 256, 256>>>(x, wq, wk, wv, wo, xh, wqkvh, woh);

    cudaFuncSetAttribute(gemm_f16_256<0>, cudaFuncAttributeMaxDynamicSharedMemorySize,
                         GEMM_SMEM);
    cudaFuncSetAttribute(gemm_f16_256<1>, cudaFuncAttributeMaxDynamicSharedMemorySize,
                         GEMM_SMEM);

    // fused QKV projection + RoPE + fp16 epilogue
    gemm_f16_256<1><<<dim3(NQKV / GBN, M / GBM), 256, GEMM_SMEM>>>(
        xh, wqkvh, nullptr, qh, kh, vh, fc, fs, M, NQKV, DIMM);

    // fp16 tensor-core flash attention
    cudaFuncSetAttribute(flash_f16, cudaFuncAttributeMaxDynamicSharedMemorySize,
                         FA_SMEM);
    flash_f16<<<dim3(SEQL / FQ, NH, BSZ), 256, FA_SMEM>>>(qh, kh, vh, attnh, SEQL);

    // output projection (fp32 out)
    gemm_f16_256<0><<<dim3(DIMM / GBN, M / GBM), 256, GEMM_SMEM>>>(
        attnh, woh, out, nullptr, nullptr, nullptr, nullptr, nullptr, M, DIMM, DIMM);
}

// round 8
// speedup vs baseline: 9.8062x; 1.1174x over previous
#include <cuda_runtime.h>
#include <cuda_fp16.h>
#include <math.h>
#include <stdint.h>

#define BSZ  2
#define SEQL 2048
#define DIMM 4096
#define NH   32
#define NKV  8
#define HD   128
#define MTOT (BSZ * SEQL)          // 4096
#define NQKV (NH * HD + 2 * NKV * HD)   // 6144

// ---------------- scratch (__device__ globals) ----------------------------
__device__ __half g_xh[MTOT * DIMM];
__device__ __half g_wqkvh[DIMM * NQKV];
__device__ __half g_woh[DIMM * DIMM];
__device__ __half g_attnh[MTOT * NH * HD];
__device__ __half g_qh[MTOT * NH * HD];
__device__ __half g_kh[MTOT * NKV * HD];
__device__ __half g_vh[MTOT * NKV * HD];

// ---------------- PTX helpers ---------------------------------------------
__device__ __forceinline__ uint32_t smem_u32(const void* p) {
    uint32_t a;
    asm("{ .reg .u64 t; cvta.to.shared.u64 t, %1; cvt.u32.u64 %0, t; }"
        : "=r"(a) : "l"(p));
    return a;
}
__device__ __forceinline__ void cp_async16(uint32_t dst, const void* src) {
    asm volatile("cp.async.cg.shared.global [%0], [%1], 16;" :: "r"(dst), "l"(src));
}
#define CP_COMMIT() asm volatile("cp.async.commit_group;" ::: "memory")
#define CP_WAIT(n)  asm volatile("cp.async.wait_group %0;" :: "n"(n) : "memory")

#define LDSM_X4(R, addr) \
    asm volatile("ldmatrix.sync.aligned.m8n8.x4.shared.b16 {%0,%1,%2,%3}, [%4];" \
        : "=r"((R)[0]), "=r"((R)[1]), "=r"((R)[2]), "=r"((R)[3]) : "r"(addr))
#define LDSM_X4_T(R, addr) \
    asm volatile("ldmatrix.sync.aligned.m8n8.x4.trans.shared.b16 {%0,%1,%2,%3}, [%4];" \
        : "=r"((R)[0]), "=r"((R)[1]), "=r"((R)[2]), "=r"((R)[3]) : "r"(addr))

#define MMA16816(D, A, B0, B1) \
    asm volatile("mma.sync.aligned.m16n8k16.row.col.f32.f16.f16.f32 " \
        "{%0,%1,%2,%3}, {%4,%5,%6,%7}, {%8,%9}, {%0,%1,%2,%3};" \
        : "+f"((D)[0]), "+f"((D)[1]), "+f"((D)[2]), "+f"((D)[3]) \
        : "r"((A)[0]), "r"((A)[1]), "r"((A)[2]), "r"((A)[3]), "r"(B0), "r"(B1))

// ---------------- fp16 mma.sync GEMM, 128x128, 3 stages, 2 CTAs/SM --------
// MODE 0: C fp32 out. MODE 1: fused RoPE + fp16 split epilogue (q|k|v).
#define GBM 128
#define GBN 128
#define GBK 64
#define GST 3
#define A_STAGE 16384                      // 128 rows * 128 B
#define B_STAGE 16384                      // 64 rows * 2 blocks * 128 B
#define STAGE_BYTES (A_STAGE + B_STAGE)    // 32768
#define GEMM_SMEM (GST * STAGE_BYTES)      // 98304

template<int MODE>
__global__ __launch_bounds__(256, 2) void gemm_f16_128(
    const __half* __restrict__ A, const __half* __restrict__ B,
    float* __restrict__ C,
    __half* __restrict__ Qd, __half* __restrict__ Kd, __half* __restrict__ Vd,
    const float* __restrict__ cosb, const float* __restrict__ sinb,
    int M, int N, int K)
{
    extern __shared__ char smem[];
    const uint32_t sb = smem_u32(smem);
    const int tid  = threadIdx.x;
    const int lane = tid & 31;
    const int wid  = tid >> 5;
    const int mt   = blockIdx.y * GBM;
    const int nt   = blockIdx.x * GBN;
    const int wm   = (wid >> 2) * 64;   // 2x4 warp grid, 64x32 warp tile
    const int wn   = (wid & 3) * 32;
    const int NK   = K / GBK;

    float acc[4][4][4];
#pragma unroll
    for (int i = 0; i < 4; i++)
#pragma unroll
        for (int j = 0; j < 4; j++)
#pragma unroll
            for (int c = 0; c < 4; c++) acc[i][j][c] = 0.f;

    auto load_stage = [&](int kt, int s) {
        const uint32_t as = sb + s * STAGE_BYTES;
        const uint32_t bs = as + A_STAGE;
        const __half* Ag = A + (size_t)mt * K + kt * GBK;
        const __half* Bg = B + (size_t)(kt * GBK) * N + nt;
#pragma unroll
        for (int i = 0; i < 4; i++) {          // A: 1024 16B chunks
            int id = tid + i * 256;
            int r = id >> 3, c = id & 7;
            cp_async16(as + r * 128 + ((c ^ (r & 7)) << 4),
                       Ag + (size_t)r * K + c * 8);
        }
#pragma unroll
        for (int i = 0; i < 4; i++) {          // B: 1024 16B chunks
            int id = tid + i * 256;
            int r = id >> 4, c = id & 15;
            uint32_t dst = bs + (c >> 3) * 8192 + r * 128 +
                           (((c & 7) ^ (r & 7)) << 4);
            cp_async16(dst, Bg + (size_t)r * N + c * 8);
        }
        CP_COMMIT();
    };

    load_stage(0, 0);
    load_stage(1, 1);

    const int lr = lane & 15;
    const int lq = lane >> 4;

    int st = 0;
    for (int kt = 0; kt < NK; kt++) {
        CP_WAIT(1);
        __syncthreads();
        if (kt + 2 < NK) {
            int s2 = st + 2; if (s2 >= GST) s2 -= GST;
            load_stage(kt + 2, s2);
        }

        const uint32_t as = sb + st * STAGE_BYTES;
        const uint32_t bs = as + A_STAGE;

#pragma unroll
        for (int ks = 0; ks < 4; ks++) {
            const int kk = ks * 16;
            uint32_t ar[4][4];
#pragma unroll
            for (int mf = 0; mf < 4; mf++) {
                int r = wm + mf * 16 + lr;
                LDSM_X4(ar[mf], as + r * 128 + ((((kk >> 3) + lq) ^ (r & 7)) << 4));
            }
            uint32_t br[2][4];
#pragma unroll
            for (int nf2 = 0; nf2 < 2; nf2++) {
                int n0 = wn + nf2 * 16;
                int r  = kk + lr;
                int cc = ((n0 & 63) >> 3) + lq;
                LDSM_X4_T(br[nf2], bs + ((n0 >= 64) ? 8192 : 0) + r * 128 +
                                   ((cc ^ (r & 7)) << 4));
            }
#pragma unroll
            for (int mf = 0; mf < 4; mf++)
#pragma unroll
                for (int nf = 0; nf < 4; nf++) {
                    uint32_t b0 = br[nf >> 1][(nf & 1) * 2];
                    uint32_t b1 = br[nf >> 1][(nf & 1) * 2 + 1];
                    MMA16816(acc[mf][nf], ar[mf], b0, b1);
                }
        }
        __syncthreads();
        if (++st == GST) st = 0;
    }

    const int g   = lane >> 2;
    const int tq  = lane & 3;

    if (MODE == 0) {
#pragma unroll
        for (int mf = 0; mf < 4; mf++) {
            int row0 = mt + wm + mf * 16 + g;
#pragma unroll
            for (int nf = 0; nf < 4; nf++) {
                int col = nt + wn + nf * 8 + tq * 2;
                *(float2*)(C + (size_t)row0 * N + col) =
                    make_float2(acc[mf][nf][0], acc[mf][nf][1]);
                *(float2*)(C + (size_t)(row0 + 8) * N + col) =
                    make_float2(acc[mf][nf][2], acc[mf][nf][3]);
            }
        }
    } else {
        // region: q cols [0,4096), k [4096,5120), v [5120,6144) — tile-aligned
        const int region = (nt >= 5 * 1024) ? 2 : (nt >= 4 * 1024 ? 1 : 0);
        __half* dst = region == 0 ? Qd : (region == 1 ? Kd : Vd);
        const int ld = region == 0 ? NH * HD : NKV * HD;
        const int cb = nt - (region == 0 ? 0 : (region == 1 ? 4096 : 5120));
        const bool dorope = (region < 2);
#pragma unroll
        for (int mf = 0; mf < 4; mf++) {
            int r0 = mt + wm + mf * 16 + g;
            int s0 = r0 & (SEQL - 1);
            int s1 = (r0 + 8) & (SEQL - 1);
#pragma unroll
            for (int nf = 0; nf < 4; nf++) {
                int colg = wn + nf * 8 + tq * 2;
                float a0 = acc[mf][nf][0], a1 = acc[mf][nf][1];
                float a2 = acc[mf][nf][2], a3 = acc[mf][nf][3];
                __half2 h0, h1;
                if (dorope) {
                    int i = ((nt + colg) & 127) >> 1;
                    float c0 = cosb[s0 * 64 + i], n0 = sinb[s0 * 64 + i];
                    float c1 = cosb[s1 * 64 + i], n1 = sinb[s1 * 64 + i];
                    h0 = __floats2half2_rn(a0 * c0 - a1 * n0, a0 * n0 + a1 * c0);
                    h1 = __floats2half2_rn(a2 * c1 - a3 * n1, a2 * n1 + a3 * c1);
                } else {
                    h0 = __floats2half2_rn(a0, a1);
                    h1 = __floats2half2_rn(a2, a3);
                }
                *(__half2*)(dst + (size_t)r0 * ld + cb + colg) = h0;
                *(__half2*)(dst + (size_t)(r0 + 8) * ld + cb + colg) = h1;
            }
        }
    }
}

// ---------------- one fused fp32 -> fp16 convert kernel (4 chunks/thread) --
#define CNX  (MTOT * DIMM / 8)
#define CNWO (DIMM * DIMM / 8)
#define CNWQ (DIMM * NH * HD / 8)
#define CNWK (DIMM * NKV * HD / 8)
#define CTOT (CNX + CNWO + CNWQ + 2 * CNWK)
#define CQ   (CTOT / 4)

__device__ __forceinline__ uint4 cvt8(const float* p) {
    float4 v0 = ((const float4*)p)[0];
    float4 v1 = ((const float4*)p)[1];
    union { uint4 u; __half2 h[4]; } r;
    r.h[0] = __floats2half2_rn(v0.x, v0.y);
    r.h[1] = __floats2half2_rn(v0.z, v0.w);
    r.h[2] = __floats2half2_rn(v1.x, v1.y);
    r.h[3] = __floats2half2_rn(v1.z, v1.w);
    return r.u;
}

__device__ __forceinline__ void do_chunk(
    int i, const float* x, const float* wq, const float* wk,
    const float* wv, const float* wo,
    __half* xh, __half* wqkvh, __half* woh)
{
    if (i < CNX) {
        ((uint4*)xh)[i] = cvt8(x + (size_t)i * 8);
    } else if (i < CNX + CNWO) {
        int j = i - CNX;
        ((uint4*)woh)[j] = cvt8(wo + (size_t)j * 8);
    } else if (i < CNX + CNWO + CNWQ) {
        int j = i - CNX - CNWO;
        int r = j >> 9, c = j & 511;
        *(uint4*)(wqkvh + (size_t)r * NQKV + c * 8) = cvt8(wq + (size_t)j * 8);
    } else if (i < CNX + CNWO + CNWQ + CNWK) {
        int j = i - CNX - CNWO - CNWQ;
        int r = j >> 7, c = j & 127;
        *(uint4*)(wqkvh + (size_t)r * NQKV + 4096 + c * 8) = cvt8(wk + (size_t)j * 8);
    } else {
        int j = i - CNX - CNWO - CNWQ - CNWK;
        int r = j >> 7, c = j & 127;
        *(uint4*)(wqkvh + (size_t)r * NQKV + 5120 + c * 8) = cvt8(wv + (size_t)j * 8);
    }
}

__global__ void convert_all(const float* __restrict__ x,
                            const float* __restrict__ wq,
                            const float* __restrict__ wk,
                            const float* __restrict__ wv,
                            const float* __restrict__ wo,
                            __half* __restrict__ xh,
                            __half* __restrict__ wqkvh,
                            __half* __restrict__ woh)
{
    int i = blockIdx.x * blockDim.x + threadIdx.x;
    if (i >= CQ) return;
    do_chunk(i,          x, wq, wk, wv, wo, xh, wqkvh, woh);
    do_chunk(i + CQ,     x, wq, wk, wv, wo, xh, wqkvh, woh);
    do_chunk(i + 2 * CQ, x, wq, wk, wv, wo, xh, wqkvh, woh);
    do_chunk(i + 3 * CQ, x, wq, wk, wv, wo, xh, wqkvh, woh);
}

// ---------------- fp16 tensor-core flash attention -------------------------
#define FQ 128
#define FK 64
#define QBYTES   (FQ * 256)
#define KVSTAGE  (FK * 256 * 2)
#define FA_SMEM  (QBYTES + 2 * KVSTAGE)

__device__ __forceinline__ uint32_t swz(uint32_t c, uint32_t r) {
    return ((c ^ (r & 7)) & 7) | (c & 8);
}

__global__ __launch_bounds__(256, 1) void flash_f16(
    const __half* __restrict__ Qh, const __half* __restrict__ Kh,
    const __half* __restrict__ Vh, __half* __restrict__ Oh, int seq)
{
    extern __shared__ char smc[];
    const uint32_t sb = smem_u32(smc);
    const uint32_t Qs = sb;

    const int qt = blockIdx.x, h = blockIdx.y, b = blockIdx.z;
    const int kvh = h >> 2;
    const int tid = threadIdx.x, lane = tid & 31, wid = tid >> 5;
    const int lr = lane & 15, lq = lane >> 4;
    const int g = lane >> 2, tq = lane & 3;
    const float scale = 0.08838834764831845f;

    const __half* Qg = Qh + ((size_t)(b * seq + qt * FQ) * NH + h) * HD;
    const __half* Kg = Kh + ((size_t)b * seq * NKV + kvh) * HD;
    const __half* Vg = Vh + ((size_t)b * seq * NKV + kvh) * HD;

#pragma unroll
    for (int i = 0; i < 8; i++) {
        int id = tid + i * 256;
        int r = id >> 4, c = id & 15;
        cp_async16(Qs + r * 256 + swz(c, r) * 16, Qg + (size_t)r * (NH * HD) + c * 8);
    }
    CP_COMMIT();

    auto load_kv = [&](int kt, int s) {
        uint32_t ks = sb + QBYTES + s * KVSTAGE;
        uint32_t vs = ks + FK * 256;
        const __half* kg = Kg + (size_t)(kt * FK) * (NKV * HD);
        const __half* vg = Vg + (size_t)(kt * FK) * (NKV * HD);
#pragma unroll
        for (int i = 0; i < 4; i++) {
            int id = tid + i * 256;
            int r = id >> 4, c = id & 15;
            uint32_t off = r * 256 + swz(c, r) * 16;
            cp_async16(ks + off, kg + (size_t)r * (NKV * HD) + c * 8);
            cp_async16(vs + off, vg + (size_t)r * (NKV * HD) + c * 8);
        }
        CP_COMMIT();
    };

    const int ntiles = 2 * qt + 2;
    load_kv(0, 0);

    float acc_o[16][4];
#pragma unroll
    for (int d = 0; d < 16; d++)
#pragma unroll
        for (int c = 0; c < 4; c++) acc_o[d][c] = 0.f;
    float mrow[2] = {-1e30f, -1e30f};
    float lrow[2] = {0.f, 0.f};

    const int row0 = qt * FQ + wid * 16 + g;

    for (int kt = 0; kt < ntiles; kt++) {
        if (kt + 1 < ntiles) { load_kv(kt + 1, (kt + 1) & 1); CP_WAIT(1); }
        else                 { CP_WAIT(0); }
        __syncthreads();

        const uint32_t ks = sb + QBYTES + (kt & 1) * KVSTAGE;
        const uint32_t vs = ks + FK * 256;

        float accs[8][4];
#pragma unroll
        for (int j = 0; j < 8; j++)
#pragma unroll
            for (int c = 0; c < 4; c++) accs[j][c] = 0.f;

#pragma unroll
        for (int d = 0; d < 8; d++) {
            uint32_t a[4];
            {
                int r = wid * 16 + lr;
                LDSM_X4(a, Qs + r * 256 + swz(d * 2 + lq, r) * 16);
            }
#pragma unroll
            for (int n = 0; n < 4; n++) {
                uint32_t kb[4];
                int r = n * 16 + lr;
                LDSM_X4(kb, ks + r * 256 + swz(d * 2 + lq, r) * 16);
                MMA16816(accs[n * 2],     a, kb[0], kb[2]);
                MMA16816(accs[n * 2 + 1], a, kb[1], kb[3]);
            }
        }

        const bool need_mask = (kt >= 2 * qt);
#pragma unroll
        for (int rr = 0; rr < 2; rr++) {
            const int grow = row0 + rr * 8;
            float mx = mrow[rr];
#pragma unroll
            for (int j = 0; j < 8; j++) {
                float s0 = accs[j][rr * 2] * scale;
                float s1 = accs[j][rr * 2 + 1] * scale;
                if (need_mask) {
                    int c0 = kt * FK + j * 8 + tq * 2;
                    if (c0 > grow)     s0 = -1e30f;
                    if (c0 + 1 > grow) s1 = -1e30f;
                }
                accs[j][rr * 2]     = s0;
                accs[j][rr * 2 + 1] = s1;
                mx = fmaxf(mx, fmaxf(s0, s1));
            }
            mx = fmaxf(mx, __shfl_xor_sync(0xFFFFFFFFu, mx, 1));
            mx = fmaxf(mx, __shfl_xor_sync(0xFFFFFFFFu, mx, 2));
            float corr = __expf(mrow[rr] - mx);
            mrow[rr] = mx;
            float ls = 0.f;
#pragma unroll
            for (int j = 0; j < 8; j++) {
                float p0 = __expf(accs[j][rr * 2] - mx);
                float p1 = __expf(accs[j][rr * 2 + 1] - mx);
                accs[j][rr * 2]     = p0;
                accs[j][rr * 2 + 1] = p1;
                ls += p0 + p1;
            }
            ls += __shfl_xor_sync(0xFFFFFFFFu, ls, 1);
            ls += __shfl_xor_sync(0xFFFFFFFFu, ls, 2);
            lrow[rr] = lrow[rr] * corr + ls;
#pragma unroll
            for (int d = 0; d < 16; d++) {
                acc_o[d][rr * 2]     *= corr;
                acc_o[d][rr * 2 + 1] *= corr;
            }
        }

        uint32_t p[8][2];
#pragma unroll
        for (int j = 0; j < 8; j++) {
            __half2 h0 = __floats2half2_rn(accs[j][0], accs[j][1]);
            __half2 h1 = __floats2half2_rn(accs[j][2], accs[j][3]);
            p[j][0] = *(uint32_t*)&h0;
            p[j][1] = *(uint32_t*)&h1;
        }

#pragma unroll
        for (int kk = 0; kk < 4; kk++) {
            uint32_t a[4] = {p[kk * 2][0], p[kk * 2][1],
                             p[kk * 2 + 1][0], p[kk * 2 + 1][1]};
#pragma unroll
            for (int dn = 0; dn < 8; dn++) {
                uint32_t vb[4];
                int r = kk * 16 + lr;
                LDSM_X4_T(vb, vs + r * 256 + swz(dn * 2 + lq, r) * 16);
                MMA16816(acc_o[dn * 2],     a, vb[0], vb[1]);
                MMA16816(acc_o[dn * 2 + 1], a, vb[2], vb[3]);
            }
        }
        __syncthreads();
    }

    const float il0 = 1.f / lrow[0];
    const float il1 = 1.f / lrow[1];
    __half* Og = Oh + ((size_t)(b * seq + row0) * NH + h) * HD;
#pragma unroll
    for (int dn = 0; dn < 16; dn++) {
        int d = dn * 8 + tq * 2;
        *(__half2*)(Og + d) =
            __floats2half2_rn(acc_o[dn][0] * il0, acc_o[dn][1] * il0);
        *(__half2*)(Og + (size_t)8 * (NH * HD) + d) =
            __floats2half2_rn(acc_o[dn][2] * il1, acc_o[dn][3] * il1);
    }
}

// ---------------- host side ------------------------------------------------
extern "C" void kernel_launch(void* const* d_in, const int* in_sizes, int n_in,
                              void* d_out, int out_size)
{
    const float* x  = (const float*)d_in[0];
    const float* wq = (const float*)d_in[1];
    const float* wk = (const float*)d_in[2];
    const float* wv = (const float*)d_in[3];
    const float* wo = (const float*)d_in[4];
    const float* fc = (const float*)d_in[7];
    const float* fs = (const float*)d_in[8];
    float* out = (float*)d_out;

    __half *xh, *wqkvh, *woh, *attnh, *qh, *kh, *vh;
    cudaGetSymbolAddress((void**)&xh,    g_xh);
    cudaGetSymbolAddress((void**)&wqkvh, g_wqkvh);
    cudaGetSymbolAddress((void**)&woh,   g_woh);
    cudaGetSymbolAddress((void**)&attnh, g_attnh);
    cudaGetSymbolAddress((void**)&qh,    g_qh);
    cudaGetSymbolAddress((void**)&kh,    g_kh);
    cudaGetSymbolAddress((void**)&vh,    g_vh);

    const int M = MTOT;

    convert_all<<<(CQ + 255) / 256, 256>>>(x, wq, wk, wv, wo, xh, wqkvh, woh);

    cudaFuncSetAttribute(gemm_f16_128<0>, cudaFuncAttributeMaxDynamicSharedMemorySize,
                         GEMM_SMEM);
    cudaFuncSetAttribute(gemm_f16_128<1>, cudaFuncAttributeMaxDynamicSharedMemorySize,
                         GEMM_SMEM);

    // fused QKV projection + RoPE + fp16 epilogue
    gemm_f16_128<1><<<dim3(NQKV / GBN, M / GBM), 256, GEMM_SMEM>>>(
        xh, wqkvh, nullptr, qh, kh, vh, fc, fs, M, NQKV, DIMM);

    // fp16 tensor-core flash attention
    cudaFuncSetAttribute(flash_f16, cudaFuncAttributeMaxDynamicSharedMemorySize,
                         FA_SMEM);
    flash_f16<<<dim3(SEQL / FQ, NH, BSZ), 256, FA_SMEM>>>(qh, kh, vh, attnh, SEQL);

    // output projection (fp32 out)
    gemm_f16_128<0><<<dim3(DIMM / GBN, M / GBM), 256, GEMM_SMEM>>>(
        attnh, woh, out, nullptr, nullptr, nullptr, nullptr, nullptr, M, DIMM, DIMM);
}

// round 9
// speedup vs baseline: 9.9502x; 1.0147x over previous
#include <cuda_runtime.h>
#include <cuda_fp16.h>
#include <math.h>
#include <stdint.h>

#define BSZ  2
#define SEQL 2048
#define DIMM 4096
#define NH   32
#define NKV  8
#define HD   128
#define MTOT (BSZ * SEQL)          // 4096
#define NQKV (NH * HD + 2 * NKV * HD)   // 6144

// ---------------- scratch (__device__ globals) ----------------------------
__device__ __half g_xh[MTOT * DIMM];
__device__ __half g_wqkvh[DIMM * NQKV];
__device__ __half g_woh[DIMM * DIMM];
__device__ __half g_attnh[MTOT * NH * HD];
__device__ __half g_qh[MTOT * NH * HD];
__device__ __half g_kh[MTOT * NKV * HD];
__device__ __half g_vh[MTOT * NKV * HD];

// ---------------- PTX helpers ---------------------------------------------
__device__ __forceinline__ uint32_t smem_u32(const void* p) {
    uint32_t a;
    asm("{ .reg .u64 t; cvta.to.shared.u64 t, %1; cvt.u32.u64 %0, t; }"
        : "=r"(a) : "l"(p));
    return a;
}
__device__ __forceinline__ void cp_async16(uint32_t dst, const void* src) {
    asm volatile("cp.async.cg.shared.global [%0], [%1], 16;" :: "r"(dst), "l"(src));
}
#define CP_COMMIT() asm volatile("cp.async.commit_group;" ::: "memory")
#define CP_WAIT(n)  asm volatile("cp.async.wait_group %0;" :: "n"(n) : "memory")

#define LDSM_X4(R, addr) \
    asm volatile("ldmatrix.sync.aligned.m8n8.x4.shared.b16 {%0,%1,%2,%3}, [%4];" \
        : "=r"((R)[0]), "=r"((R)[1]), "=r"((R)[2]), "=r"((R)[3]) : "r"(addr))
#define LDSM_X4_T(R, addr) \
    asm volatile("ldmatrix.sync.aligned.m8n8.x4.trans.shared.b16 {%0,%1,%2,%3}, [%4];" \
        : "=r"((R)[0]), "=r"((R)[1]), "=r"((R)[2]), "=r"((R)[3]) : "r"(addr))

#define MMA16816(D, A, B0, B1) \
    asm volatile("mma.sync.aligned.m16n8k16.row.col.f32.f16.f16.f32 " \
        "{%0,%1,%2,%3}, {%4,%5,%6,%7}, {%8,%9}, {%0,%1,%2,%3};" \
        : "+f"((D)[0]), "+f"((D)[1]), "+f"((D)[2]), "+f"((D)[3]) \
        : "r"((A)[0]), "r"((A)[1]), "r"((A)[2]), "r"((A)[3]), "r"(B0), "r"(B1))

// ---------------- fp16 mma.sync GEMM, 128x128, 3 stages, 2 CTAs/SM --------
// MODE 0: C fp32 out. MODE 1: fused RoPE + fp16 split epilogue (q|k|v).
#define GBM 128
#define GBN 128
#define GBK 64
#define GST 3
#define A_STAGE 16384                      // 128 rows * 128 B
#define B_STAGE 16384                      // 64 rows * 2 blocks * 128 B
#define STAGE_BYTES (A_STAGE + B_STAGE)    // 32768
#define GEMM_SMEM (GST * STAGE_BYTES)      // 98304

template<int MODE>
__global__ __launch_bounds__(256, 2) void gemm_f16_128(
    const __half* __restrict__ A, const __half* __restrict__ B,
    float* __restrict__ C,
    __half* __restrict__ Qd, __half* __restrict__ Kd, __half* __restrict__ Vd,
    const float* __restrict__ cosb, const float* __restrict__ sinb,
    int M, int N, int K)
{
    extern __shared__ char smem[];
    const uint32_t sb = smem_u32(smem);
    const int tid  = threadIdx.x;
    const int lane = tid & 31;
    const int wid  = tid >> 5;
    const int mt   = blockIdx.y * GBM;
    const int nt   = blockIdx.x * GBN;
    const int wm   = (wid >> 2) * 64;   // 2x4 warp grid, 64x32 warp tile
    const int wn   = (wid & 3) * 32;
    const int NK   = K / GBK;

    float acc[4][4][4];
#pragma unroll
    for (int i = 0; i < 4; i++)
#pragma unroll
        for (int j = 0; j < 4; j++)
#pragma unroll
            for (int c = 0; c < 4; c++) acc[i][j][c] = 0.f;

    auto load_stage = [&](int kt, int s) {
        const uint32_t as = sb + s * STAGE_BYTES;
        const uint32_t bs = as + A_STAGE;
        const __half* Ag = A + (size_t)mt * K + kt * GBK;
        const __half* Bg = B + (size_t)(kt * GBK) * N + nt;
#pragma unroll
        for (int i = 0; i < 4; i++) {          // A: 1024 16B chunks
            int id = tid + i * 256;
            int r = id >> 3, c = id & 7;
            cp_async16(as + r * 128 + ((c ^ (r & 7)) << 4),
                       Ag + (size_t)r * K + c * 8);
        }
#pragma unroll
        for (int i = 0; i < 4; i++) {          // B: 1024 16B chunks
            int id = tid + i * 256;
            int r = id >> 4, c = id & 15;
            uint32_t dst = bs + (c >> 3) * 8192 + r * 128 +
                           (((c & 7) ^ (r & 7)) << 4);
            cp_async16(dst, Bg + (size_t)r * N + c * 8);
        }
        CP_COMMIT();
    };

    load_stage(0, 0);
    load_stage(1, 1);

    const int lr = lane & 15;
    const int lq = lane >> 4;

    int st = 0;
    for (int kt = 0; kt < NK; kt++) {
        CP_WAIT(1);
        __syncthreads();                       // single barrier per iteration
        if (kt + 2 < NK) {
            int s2 = st + 2; if (s2 >= GST) s2 -= GST;
            load_stage(kt + 2, s2);
        }

        const uint32_t as = sb + st * STAGE_BYTES;
        const uint32_t bs = as + A_STAGE;

#pragma unroll
        for (int ks = 0; ks < 4; ks++) {
            const int kk = ks * 16;
            uint32_t ar[4][4];
#pragma unroll
            for (int mf = 0; mf < 4; mf++) {
                int r = wm + mf * 16 + lr;
                LDSM_X4(ar[mf], as + r * 128 + ((((kk >> 3) + lq) ^ (r & 7)) << 4));
            }
            uint32_t br[2][4];
#pragma unroll
            for (int nf2 = 0; nf2 < 2; nf2++) {
                int n0 = wn + nf2 * 16;
                int r  = kk + lr;
                int cc = ((n0 & 63) >> 3) + lq;
                LDSM_X4_T(br[nf2], bs + ((n0 >= 64) ? 8192 : 0) + r * 128 +
                                   ((cc ^ (r & 7)) << 4));
            }
#pragma unroll
            for (int mf = 0; mf < 4; mf++)
#pragma unroll
                for (int nf = 0; nf < 4; nf++) {
                    uint32_t b0 = br[nf >> 1][(nf & 1) * 2];
                    uint32_t b1 = br[nf >> 1][(nf & 1) * 2 + 1];
                    MMA16816(acc[mf][nf], ar[mf], b0, b1);
                }
        }
        if (++st == GST) st = 0;
    }

    const int g   = lane >> 2;
    const int tq  = lane & 3;

    if (MODE == 0) {
#pragma unroll
        for (int mf = 0; mf < 4; mf++) {
            int row0 = mt + wm + mf * 16 + g;
#pragma unroll
            for (int nf = 0; nf < 4; nf++) {
                int col = nt + wn + nf * 8 + tq * 2;
                *(float2*)(C + (size_t)row0 * N + col) =
                    make_float2(acc[mf][nf][0], acc[mf][nf][1]);
                *(float2*)(C + (size_t)(row0 + 8) * N + col) =
                    make_float2(acc[mf][nf][2], acc[mf][nf][3]);
            }
        }
    } else {
        // region: q cols [0,4096), k [4096,5120), v [5120,6144) — tile-aligned
        const int region = (nt >= 5 * 1024) ? 2 : (nt >= 4 * 1024 ? 1 : 0);
        __half* dst = region == 0 ? Qd : (region == 1 ? Kd : Vd);
        const int ld = region == 0 ? NH * HD : NKV * HD;
        const int cb = nt - (region == 0 ? 0 : (region == 1 ? 4096 : 5120));
        const bool dorope = (region < 2);
#pragma unroll
        for (int mf = 0; mf < 4; mf++) {
            int r0 = mt + wm + mf * 16 + g;
            int s0 = r0 & (SEQL - 1);
            int s1 = (r0 + 8) & (SEQL - 1);
#pragma unroll
            for (int nf = 0; nf < 4; nf++) {
                int colg = wn + nf * 8 + tq * 2;
                float a0 = acc[mf][nf][0], a1 = acc[mf][nf][1];
                float a2 = acc[mf][nf][2], a3 = acc[mf][nf][3];
                __half2 h0, h1;
                if (dorope) {
                    int i = ((nt + colg) & 127) >> 1;
                    float c0 = cosb[s0 * 64 + i], n0 = sinb[s0 * 64 + i];
                    float c1 = cosb[s1 * 64 + i], n1 = sinb[s1 * 64 + i];
                    h0 = __floats2half2_rn(a0 * c0 - a1 * n0, a0 * n0 + a1 * c0);
                    h1 = __floats2half2_rn(a2 * c1 - a3 * n1, a2 * n1 + a3 * c1);
                } else {
                    h0 = __floats2half2_rn(a0, a1);
                    h1 = __floats2half2_rn(a2, a3);
                }
                *(__half2*)(dst + (size_t)r0 * ld + cb + colg) = h0;
                *(__half2*)(dst + (size_t)(r0 + 8) * ld + cb + colg) = h1;
            }
        }
    }
}

// ---------------- one fused fp32 -> fp16 convert kernel (4 chunks/thread) --
#define CNX  (MTOT * DIMM / 8)
#define CNWO (DIMM * DIMM / 8)
#define CNWQ (DIMM * NH * HD / 8)
#define CNWK (DIMM * NKV * HD / 8)
#define CTOT (CNX + CNWO + CNWQ + 2 * CNWK)
#define CQ   (CTOT / 4)

__device__ __forceinline__ uint4 cvt8(const float* p) {
    float4 v0 = ((const float4*)p)[0];
    float4 v1 = ((const float4*)p)[1];
    union { uint4 u; __half2 h[4]; } r;
    r.h[0] = __floats2half2_rn(v0.x, v0.y);
    r.h[1] = __floats2half2_rn(v0.z, v0.w);
    r.h[2] = __floats2half2_rn(v1.x, v1.y);
    r.h[3] = __floats2half2_rn(v1.z, v1.w);
    return r.u;
}

__device__ __forceinline__ void do_chunk(
    int i, const float* x, const float* wq, const float* wk,
    const float* wv, const float* wo,
    __half* xh, __half* wqkvh, __half* woh)
{
    if (i < CNX) {
        ((uint4*)xh)[i] = cvt8(x + (size_t)i * 8);
    } else if (i < CNX + CNWO) {
        int j = i - CNX;
        ((uint4*)woh)[j] = cvt8(wo + (size_t)j * 8);
    } else if (i < CNX + CNWO + CNWQ) {
        int j = i - CNX - CNWO;
        int r = j >> 9, c = j & 511;
        *(uint4*)(wqkvh + (size_t)r * NQKV + c * 8) = cvt8(wq + (size_t)j * 8);
    } else if (i < CNX + CNWO + CNWQ + CNWK) {
        int j = i - CNX - CNWO - CNWQ;
        int r = j >> 7, c = j & 127;
        *(uint4*)(wqkvh + (size_t)r * NQKV + 4096 + c * 8) = cvt8(wk + (size_t)j * 8);
    } else {
        int j = i - CNX - CNWO - CNWQ - CNWK;
        int r = j >> 7, c = j & 127;
        *(uint4*)(wqkvh + (size_t)r * NQKV + 5120 + c * 8) = cvt8(wv + (size_t)j * 8);
    }
}

__global__ void convert_all(const float* __restrict__ x,
                            const float* __restrict__ wq,
                            const float* __restrict__ wk,
                            const float* __restrict__ wv,
                            const float* __restrict__ wo,
                            __half* __restrict__ xh,
                            __half* __restrict__ wqkvh,
                            __half* __restrict__ woh)
{
    int i = blockIdx.x * blockDim.x + threadIdx.x;
    if (i >= CQ) return;
    do_chunk(i,          x, wq, wk, wv, wo, xh, wqkvh, woh);
    do_chunk(i + CQ,     x, wq, wk, wv, wo, xh, wqkvh, woh);
    do_chunk(i + 2 * CQ, x, wq, wk, wv, wo, xh, wqkvh, woh);
    do_chunk(i + 3 * CQ, x, wq, wk, wv, wo, xh, wqkvh, woh);
}

// ---------------- fp16 tensor-core flash attention, FK=128 -----------------
#define FQ 128
#define FK 128
#define QBYTES   (FQ * 256)                // 32768
#define KVSTAGE  (FK * 256 * 2)            // 65536 (K 32KB + V 32KB)
#define FA_SMEM  (QBYTES + 2 * KVSTAGE)    // 163840

__device__ __forceinline__ uint32_t swz(uint32_t c, uint32_t r) {
    return ((c ^ (r & 7)) & 7) | (c & 8);
}

__global__ __launch_bounds__(256, 1) void flash_f16(
    const __half* __restrict__ Qh, const __half* __restrict__ Kh,
    const __half* __restrict__ Vh, __half* __restrict__ Oh, int seq)
{
    extern __shared__ char smc[];
    const uint32_t sb = smem_u32(smc);
    const uint32_t Qs = sb;

    const int nq = seq / FQ;
    const int qt = nq - 1 - blockIdx.x;       // longest CTAs first
    const int h = blockIdx.y, b = blockIdx.z;
    const int kvh = h >> 2;
    const int tid = threadIdx.x, lane = tid & 31, wid = tid >> 5;
    const int lr = lane & 15, lq = lane >> 4;
    const int g = lane >> 2, tq = lane & 3;
    const float scale = 0.08838834764831845f;

    const __half* Qg = Qh + ((size_t)(b * seq + qt * FQ) * NH + h) * HD;
    const __half* Kg = Kh + ((size_t)b * seq * NKV + kvh) * HD;
    const __half* Vg = Vh + ((size_t)b * seq * NKV + kvh) * HD;

#pragma unroll
    for (int i = 0; i < 8; i++) {
        int id = tid + i * 256;
        int r = id >> 4, c = id & 15;
        cp_async16(Qs + r * 256 + swz(c, r) * 16, Qg + (size_t)r * (NH * HD) + c * 8);
    }
    CP_COMMIT();

    auto load_kv = [&](int kt, int s) {
        uint32_t ks = sb + QBYTES + s * KVSTAGE;
        uint32_t vs = ks + FK * 256;
        const __half* kg = Kg + (size_t)(kt * FK) * (NKV * HD);
        const __half* vg = Vg + (size_t)(kt * FK) * (NKV * HD);
#pragma unroll
        for (int i = 0; i < 8; i++) {
            int id = tid + i * 256;
            int r = id >> 4, c = id & 15;
            uint32_t off = r * 256 + swz(c, r) * 16;
            cp_async16(ks + off, kg + (size_t)r * (NKV * HD) + c * 8);
            cp_async16(vs + off, vg + (size_t)r * (NKV * HD) + c * 8);
        }
        CP_COMMIT();
    };

    const int ntiles = qt + 1;
    load_kv(0, 0);

    float acc_o[16][4];
#pragma unroll
    for (int d = 0; d < 16; d++)
#pragma unroll
        for (int c = 0; c < 4; c++) acc_o[d][c] = 0.f;
    float mrow[2] = {-1e30f, -1e30f};
    float lrow[2] = {0.f, 0.f};

    const int row0 = qt * FQ + wid * 16 + g;

    for (int kt = 0; kt < ntiles; kt++) {
        if (kt + 1 < ntiles) { load_kv(kt + 1, (kt + 1) & 1); CP_WAIT(1); }
        else                 { CP_WAIT(0); }
        __syncthreads();

        const uint32_t ks = sb + QBYTES + (kt & 1) * KVSTAGE;
        const uint32_t vs = ks + FK * 256;

        // ---- S = Q @ K^T  (warp tile 16 x 128) ----
        float accs[16][4];
#pragma unroll
        for (int j = 0; j < 16; j++)
#pragma unroll
            for (int c = 0; c < 4; c++) accs[j][c] = 0.f;

#pragma unroll
        for (int d = 0; d < 8; d++) {
            uint32_t a[4];
            {
                int r = wid * 16 + lr;
                LDSM_X4(a, Qs + r * 256 + swz(d * 2 + lq, r) * 16);
            }
#pragma unroll
            for (int n = 0; n < 8; n++) {
                uint32_t kb[4];
                int r = n * 16 + lr;
                LDSM_X4(kb, ks + r * 256 + swz(d * 2 + lq, r) * 16);
                MMA16816(accs[n * 2],     a, kb[0], kb[2]);
                MMA16816(accs[n * 2 + 1], a, kb[1], kb[3]);
            }
        }

        // ---- online softmax ----
        const bool need_mask = (kt == qt);
#pragma unroll
        for (int rr = 0; rr < 2; rr++) {
            const int grow = row0 + rr * 8;
            float mx = mrow[rr];
#pragma unroll
            for (int j = 0; j < 16; j++) {
                float s0 = accs[j][rr * 2] * scale;
                float s1 = accs[j][rr * 2 + 1] * scale;
                if (need_mask) {
                    int c0 = kt * FK + j * 8 + tq * 2;
                    if (c0 > grow)     s0 = -1e30f;
                    if (c0 + 1 > grow) s1 = -1e30f;
                }
                accs[j][rr * 2]     = s0;
                accs[j][rr * 2 + 1] = s1;
                mx = fmaxf(mx, fmaxf(s0, s1));
            }
            mx = fmaxf(mx, __shfl_xor_sync(0xFFFFFFFFu, mx, 1));
            mx = fmaxf(mx, __shfl_xor_sync(0xFFFFFFFFu, mx, 2));
            float corr = __expf(mrow[rr] - mx);
            mrow[rr] = mx;
            float ls = 0.f;
#pragma unroll
            for (int j = 0; j < 16; j++) {
                float p0 = __expf(accs[j][rr * 2] - mx);
                float p1 = __expf(accs[j][rr * 2 + 1] - mx);
                accs[j][rr * 2]     = p0;
                accs[j][rr * 2 + 1] = p1;
                ls += p0 + p1;
            }
            ls += __shfl_xor_sync(0xFFFFFFFFu, ls, 1);
            ls += __shfl_xor_sync(0xFFFFFFFFu, ls, 2);
            lrow[rr] = lrow[rr] * corr + ls;
#pragma unroll
            for (int d = 0; d < 16; d++) {
                acc_o[d][rr * 2]     *= corr;
                acc_o[d][rr * 2 + 1] *= corr;
            }
        }

        // ---- P fp16 (C-frag == A-frag identity) ----
        uint32_t p[16][2];
#pragma unroll
        for (int j = 0; j < 16; j++) {
            __half2 h0 = __floats2half2_rn(accs[j][0], accs[j][1]);
            __half2 h1 = __floats2half2_rn(accs[j][2], accs[j][3]);
            p[j][0] = *(uint32_t*)&h0;
            p[j][1] = *(uint32_t*)&h1;
        }

        // ---- O += P @ V ----
#pragma unroll
        for (int kk = 0; kk < 8; kk++) {
            uint32_t a[4] = {p[kk * 2][0], p[kk * 2][1],
                             p[kk * 2 + 1][0], p[kk * 2 + 1][1]};
#pragma unroll
            for (int dn = 0; dn < 8; dn++) {
                uint32_t vb[4];
                int r = kk * 16 + lr;
                LDSM_X4_T(vb, vs + r * 256 + swz(dn * 2 + lq, r) * 16);
                MMA16816(acc_o[dn * 2],     a, vb[0], vb[1]);
                MMA16816(acc_o[dn * 2 + 1], a, vb[2], vb[3]);
            }
        }
        __syncthreads();
    }

    const float il0 = 1.f / lrow[0];
    const float il1 = 1.f / lrow[1];
    __half* Og = Oh + ((size_t)(b * seq + row0) * NH + h) * HD;
#pragma unroll
    for (int dn = 0; dn < 16; dn++) {
        int d = dn * 8 + tq * 2;
        *(__half2*)(Og + d) =
            __floats2half2_rn(acc_o[dn][0] * il0, acc_o[dn][1] * il0);
        *(__half2*)(Og + (size_t)8 * (NH * HD) + d) =
            __floats2half2_rn(acc_o[dn][2] * il1, acc_o[dn][3] * il1);
    }
}

// ---------------- host side ------------------------------------------------
extern "C" void kernel_launch(void* const* d_in, const int* in_sizes, int n_in,
                              void* d_out, int out_size)
{
    const float* x  = (const float*)d_in[0];
    const float* wq = (const float*)d_in[1];
    const float* wk = (const float*)d_in[2];
    const float* wv = (const float*)d_in[3];
    const float* wo = (const float*)d_in[4];
    const float* fc = (const float*)d_in[7];
    const float* fs = (const float*)d_in[8];
    float* out = (float*)d_out;

    __half *xh, *wqkvh, *woh, *attnh, *qh, *kh, *vh;
    cudaGetSymbolAddress((void**)&xh,    g_xh);
    cudaGetSymbolAddress((void**)&wqkvh, g_wqkvh);
    cudaGetSymbolAddress((void**)&woh,   g_woh);
    cudaGetSymbolAddress((void**)&attnh, g_attnh);
    cudaGetSymbolAddress((void**)&qh,    g_qh);
    cudaGetSymbolAddress((void**)&kh,    g_kh);
    cudaGetSymbolAddress((void**)&vh,    g_vh);

    const int M = MTOT;

    convert_all<<<(CQ + 255) / 256, 256>>>(x, wq, wk, wv, wo, xh, wqkvh, woh);

    cudaFuncSetAttribute(gemm_f16_128<0>, cudaFuncAttributeMaxDynamicSharedMemorySize,
                         GEMM_SMEM);
    cudaFuncSetAttribute(gemm_f16_128<1>, cudaFuncAttributeMaxDynamicSharedMemorySize,
                         GEMM_SMEM);

    // fused QKV projection + RoPE + fp16 epilogue
    gemm_f16_128<1><<<dim3(NQKV / GBN, M / GBM), 256, GEMM_SMEM>>>(
        xh, wqkvh, nullptr, qh, kh, vh, fc, fs, M, NQKV, DIMM);

    // fp16 tensor-core flash attention (FK=128)
    cudaFuncSetAttribute(flash_f16, cudaFuncAttributeMaxDynamicSharedMemorySize,
                         FA_SMEM);
    flash_f16<<<dim3(SEQL / FQ, NH, BSZ), 256, FA_SMEM>>>(qh, kh, vh, attnh, SEQL);

    // output projection (fp32 out)
    gemm_f16_128<0><<<dim3(DIMM / GBN, M / GBM), 256, GEMM_SMEM>>>(
        attnh, woh, out, nullptr, nullptr, nullptr, nullptr, nullptr, M, DIMM, DIMM);
}